// round 10
// baseline (speedup 1.0000x reference)
#include <cuda_runtime.h>
#include <cstdint>

#define NN 16
#define CC 32
#define HH 224
#define WW 224
#define HW (HH * WW)            // 50176
#define NHW (NN * HW)           // 802816
#define PW 226
#define PH 226
#define PHW (PW * PH)           // 51076
#define NPHW (NN * PHW)         // 817216
#define RR 16                   // rows per conv block (224/16 = 14 row-blocks)

// g_y layout: [n][h][group(8)][w][4ch] int8 (halved conv values).
#define GY_IDX(n, h, g, w) (((((size_t)(n) * HH + (h)) * 8 + (g)) * WW + (w)) * 4)

// ---------------- CSA helpers (single-LOP3 xor3 / majority) ----------------
__device__ __forceinline__ unsigned xor3(unsigned a, unsigned b, unsigned c) {
    unsigned r;
    asm("lop3.b32 %0, %1, %2, %3, 0x96;" : "=r"(r) : "r"(a), "r"(b), "r"(c));
    return r;
}
__device__ __forceinline__ unsigned maj3(unsigned a, unsigned b, unsigned c) {
    unsigned r;
    asm("lop3.b32 %0, %1, %2, %3, 0xE8;" : "=r"(r) : "r"(a), "r"(b), "r"(c));
    return r;
}

// ---------------- device scratch ----------------
__device__ unsigned    g_bits[NPHW];            // layer-1 input bits (padded)
__device__ signed char g_y[(size_t)NHW * 32];   // conv1 halved output (25.7 MB)
__device__ signed char g_y2[(size_t)NHW * 32];  // conv2 halved output (25.7 MB)
__device__ long long g_sum1[32], g_ssq1[32];    // stats of HALVED values
__device__ long long g_sum2[32], g_ssq2[32];
__device__ unsigned  g_wm0[288];
__device__ unsigned  g_wm1[288];

// ---------------- K0: zero BORDERS of padded bit image + masks + stats ----------
__global__ void k_prep(const float* __restrict__ w1, const float* __restrict__ w2) {
    int i = blockIdx.x * blockDim.x + threadIdx.x;
    if (i < NN * 900) {
        int img = i / 900, r = i % 900;
        int h, w;
        if (r < 226)      { h = 0;            w = r; }
        else if (r < 452) { h = 225;          w = r - 226; }
        else if (r < 676) { h = r - 452 + 1;  w = 0; }
        else              { h = r - 676 + 1;  w = 225; }
        g_bits[(size_t)img * PHW + (size_t)h * PW + w] = 0u;
    }
    if (blockIdx.x == 0) {
        int tid = threadIdx.x;
        if (tid < 288) {
            int o = tid / 9, t = tid % 9;
            unsigned m = 0;
            #pragma unroll
            for (int k = 0; k < 32; k++)
                m |= (w1[(o * 32 + k) * 9 + t] > 0.0f ? 1u : 0u) << k;
            g_wm0[tid] = m;
        } else if (tid < 576) {
            int j = tid - 288;
            int o = j / 9, t = j % 9;
            unsigned m = 0;
            #pragma unroll
            for (int k = 0; k < 32; k++)
                m |= (w2[(o * 32 + k) * 9 + t] > 0.0f ? 1u : 0u) << k;
            g_wm1[j] = m;
        } else if (tid < 608) {
            int o = tid - 576;
            g_sum1[o] = 0; g_ssq1[o] = 0;
            g_sum2[o] = 0; g_ssq2[o] = 0;
        }
    }
}

// ---------------- K1: binarize x -> packed bits ----------------
__global__ __launch_bounds__(256) void k_pack_x(const float* __restrict__ x) {
    int t = blockIdx.x * 256 + threadIdx.x;
    size_t p0 = (size_t)t * 4;
    int n = (int)(p0 / HW);
    int q = (int)(p0 % HW);
    unsigned b0 = 0, b1 = 0, b2 = 0, b3 = 0;
    #pragma unroll
    for (int c = 0; c < 32; c++) {
        const float4 v = *reinterpret_cast<const float4*>(x + ((size_t)(n * 32 + c) * HW + q));
        b0 |= (v.x > 0.0f ? 1u : 0u) << c;
        b1 |= (v.y > 0.0f ? 1u : 0u) << c;
        b2 |= (v.z > 0.0f ? 1u : 0u) << c;
        b3 |= (v.w > 0.0f ? 1u : 0u) << c;
    }
    int h = q / WW, w = q % WW;
    unsigned* d = g_bits + (size_t)n * PHW + (size_t)(h + 1) * PW + (w + 1);
    d[0] = b0; d[1] = b1; d[2] = b2; d[3] = b3;
}

// Per-channel CSA conv step (9->4 popc compressor, masks folded).
__device__ __forceinline__ int conv_ch_csa(
    const unsigned xw[9], unsigned X012, unsigned X345, unsigned X678, unsigned XAll,
    const unsigned m[9], unsigned MR0, unsigned MR1, unsigned MR2, unsigned MAll,
    int base) {
    unsigned c1 = maj3(xw[0] ^ m[0], xw[1] ^ m[1], xw[2] ^ m[2]);
    unsigned c2 = maj3(xw[3] ^ m[3], xw[4] ^ m[4], xw[5] ^ m[5]);
    unsigned c3 = maj3(xw[6] ^ m[6], xw[7] ^ m[7], xw[8] ^ m[8]);
    unsigned s1 = X012 ^ MR0;
    unsigned s2 = X345 ^ MR1;
    unsigned s3 = X678 ^ MR2;
    unsigned s4 = XAll ^ MAll;
    unsigned c4 = maj3(s1, s2, s3);
    unsigned s5 = xor3(c1, c2, c3);
    unsigned c5 = maj3(c1, c2, c3);
    int cnt = __popc(s4) + ((__popc(c4) + __popc(s5)) << 1) + (__popc(c5) << 2);
    return base - cnt;      // base = 144 + half-corrections
}

// ---------------- K2: conv layer 1 — CSA core, 4 channels/warp ------------------
__global__ __launch_bounds__(256, 2) void k_conv1() {
    int bid   = blockIdx.x;
    int n     = bid / 98;                 // 7 strips * 14 rowblocks
    int rem   = bid % 98;
    int strip = rem % 7;
    int rb    = rem / 7;
    int w0    = strip * 32;
    int h0    = rb * RR;
    int lane  = threadIdx.x;
    int g     = threadIdx.y;              // 8 warps, 4 channels each
    int cb    = g * 4;

    unsigned m[4][9], MR0[4], MR1[4], MR2[4], MAll[4];
    #pragma unroll
    for (int j = 0; j < 4; j++) {
        #pragma unroll
        for (int t = 0; t < 9; t++)
            m[j][t] = g_wm0[(cb + j) * 9 + t];
        MR0[j] = xor3(m[j][0], m[j][1], m[j][2]);
        MR1[j] = xor3(m[j][3], m[j][4], m[j][5]);
        MR2[j] = xor3(m[j][6], m[j][7], m[j][8]);
        MAll[j] = xor3(MR0[j], MR1[j], MR2[j]);
    }

    int w = w0 + lane;
    bool eL = (w == 0), eR = (w == WW - 1);

    int base[4], rctH[4], rcbH[4];
    #pragma unroll
    for (int j = 0; j < 4; j++) {
        int ch[9];
        #pragma unroll
        for (int t = 0; t < 9; t++) ch[t] = 16 - __popc(m[j][t]);   // half-corrections
        int caddH = eL ? -(ch[0] + ch[3] + ch[6]) : (eR ? -(ch[2] + ch[5] + ch[8]) : 0);
        base[j] = 144 + caddH;
        rctH[j] = -(ch[0] + ch[1] + ch[2]) + (eL ? ch[0] : 0) + (eR ? ch[2] : 0);
        rcbH[j] = -(ch[6] + ch[7] + ch[8]) + (eL ? ch[6] : 0) + (eR ? ch[8] : 0);
    }

    const unsigned* bp = g_bits + (size_t)n * PHW + (size_t)h0 * PW + w;
    unsigned xw[9];
    xw[0] = bp[0];  xw[1] = bp[1];      xw[2] = bp[2];
    xw[3] = bp[PW]; xw[4] = bp[PW + 1]; xw[5] = bp[PW + 2];

    bool top = (h0 == 0), bot = (h0 + RR == HH);
    int rs[4] = {0, 0, 0, 0};
    int rq[4] = {0, 0, 0, 0};

    #pragma unroll
    for (int rr = 0; rr < RR; rr++) {
        const unsigned* qp = bp + (size_t)(rr + 2) * PW;
        xw[6] = qp[0]; xw[7] = qp[1]; xw[8] = qp[2];

        unsigned X012 = xor3(xw[0], xw[1], xw[2]);
        unsigned X345 = xor3(xw[3], xw[4], xw[5]);
        unsigned X678 = xor3(xw[6], xw[7], xw[8]);
        unsigned XAll = xor3(X012, X345, X678);

        int hv[4];
        #pragma unroll
        for (int j = 0; j < 4; j++) {
            int b = base[j];
            if (rr == 0 && top)      b += rctH[j];
            if (rr == RR - 1 && bot) b += rcbH[j];
            hv[j] = conv_ch_csa(xw, X012, X345, X678, XAll,
                                m[j], MR0[j], MR1[j], MR2[j], MAll[j], b);
            rs[j] += hv[j];
            rq[j] += hv[j] * hv[j];
        }

        *reinterpret_cast<char4*>(g_y + GY_IDX(n, h0 + rr, g, w)) =
            make_char4((signed char)hv[0], (signed char)hv[1],
                       (signed char)hv[2], (signed char)hv[3]);

        xw[0] = xw[3]; xw[1] = xw[4]; xw[2] = xw[5];
        xw[3] = xw[6]; xw[4] = xw[7]; xw[5] = xw[8];
    }

    #pragma unroll
    for (int j = 0; j < 4; j++) {
        int s = __reduce_add_sync(0xffffffffu, rs[j]);
        int q = __reduce_add_sync(0xffffffffu, rq[j]);
        if (lane == 0) {
            atomicAdd((unsigned long long*)&g_sum1[cb + j], (unsigned long long)(long long)s);
            atomicAdd((unsigned long long*)&g_ssq1[cb + j], (unsigned long long)(long long)q);
        }
    }
}

// ---------------- K3: FUSED threshold(conv1,BN1) + conv layer 2 (CSA, 4ch/warp) -
__global__ __launch_bounds__(256, 2) void k_conv2p(const float* __restrict__ gamma,
                                                   const float* __restrict__ beta) {
    __shared__ unsigned sBits[RR + 2][35];
    __shared__ int      sTc[32];
    __shared__ unsigned sFl[32];
    __shared__ unsigned sT[8], sF[8];

    int lane = threadIdx.x;
    int g    = threadIdx.y;
    int tid  = g * 32 + lane;              // 0..255

    int bid   = blockIdx.x;
    int n     = bid / 98;
    int rem   = bid % 98;
    int strip = rem % 7;
    int rb    = rem / 7;
    int w0    = strip * 32;
    int h0    = rb * RR;

    // ---- thresholds from exact integer stats of layer 1 ----
    if (tid < 32) {
        int o = tid;
        double mean = 2.0 * (double)g_sum1[o] / (double)NHW;
        double var  = 4.0 * (double)g_ssq1[o] / (double)NHW - mean * mean;
        double inv  = rsqrt(var + 1e-5);
        double a    = (double)gamma[o] * inv;
        double cst  = (double)beta[o] - mean * a;
        int T; unsigned f;
        if (a > 0.0)      { T = (int)floor(-cst / (2.0 * a));    f = 0x00u; }
        else if (a < 0.0) { T = (int)ceil(-cst / (2.0 * a)) - 1; f = 0xFFu; }
        else              { T = (cst > 0.0) ? -128 : 127;        f = 0x00u; }
        T = max(-128, min(127, T));
        sTc[o] = T & 0xFF;
        sFl[o] = f;
    }
    __syncthreads();
    if (tid < 8) {
        sT[tid] = (unsigned)sTc[4*tid] | ((unsigned)sTc[4*tid+1] << 8)
                | ((unsigned)sTc[4*tid+2] << 16) | ((unsigned)sTc[4*tid+3] << 24);
        sF[tid] = sFl[4*tid] | (sFl[4*tid+1] << 8) | (sFl[4*tid+2] << 16) | (sFl[4*tid+3] << 24);
    }
    __syncthreads();

    // ---- stage thresholded bits (halo tile) ----
    for (int i = tid; i < (RR + 2) * 34; i += 256) {
        int hl = i / 34, wl = i % 34;
        int h = h0 - 1 + hl, w = w0 - 1 + wl;
        unsigned b = 0;
        if (h >= 0 && h < HH && w >= 0 && w < WW) {
            #pragma unroll
            for (int gg = 0; gg < 8; gg++) {
                unsigned A = *reinterpret_cast<const unsigned*>(g_y + GY_IDX(n, h, gg, w));
                unsigned mm = (__vcmpgts4(A, sT[gg]) ^ sF[gg]) & 0x01010101u;
                b |= ((unsigned)__dp4a(mm, 0x08040201u, 0u)) << (gg * 4);
            }
        }
        sBits[hl][wl] = b;
    }
    __syncthreads();

    // ---- conv from smem: CSA core, 4 channels/warp ----
    int cb = g * 4;
    unsigned m[4][9], MR0[4], MR1[4], MR2[4], MAll[4];
    #pragma unroll
    for (int j = 0; j < 4; j++) {
        #pragma unroll
        for (int t = 0; t < 9; t++)
            m[j][t] = g_wm1[(cb + j) * 9 + t];
        MR0[j] = xor3(m[j][0], m[j][1], m[j][2]);
        MR1[j] = xor3(m[j][3], m[j][4], m[j][5]);
        MR2[j] = xor3(m[j][6], m[j][7], m[j][8]);
        MAll[j] = xor3(MR0[j], MR1[j], MR2[j]);
    }

    int w = w0 + lane;
    bool eL = (w == 0), eR = (w == WW - 1);

    int base[4], rctH[4], rcbH[4];
    #pragma unroll
    for (int j = 0; j < 4; j++) {
        int ch[9];
        #pragma unroll
        for (int t = 0; t < 9; t++) ch[t] = 16 - __popc(m[j][t]);
        int caddH = eL ? -(ch[0] + ch[3] + ch[6]) : (eR ? -(ch[2] + ch[5] + ch[8]) : 0);
        base[j] = 144 + caddH;
        rctH[j] = -(ch[0] + ch[1] + ch[2]) + (eL ? ch[0] : 0) + (eR ? ch[2] : 0);
        rcbH[j] = -(ch[6] + ch[7] + ch[8]) + (eL ? ch[6] : 0) + (eR ? ch[8] : 0);
    }

    unsigned xw[9];
    xw[0] = sBits[0][lane]; xw[1] = sBits[0][lane + 1]; xw[2] = sBits[0][lane + 2];
    xw[3] = sBits[1][lane]; xw[4] = sBits[1][lane + 1]; xw[5] = sBits[1][lane + 2];

    bool top = (h0 == 0), bot = (h0 + RR == HH);
    int rs[4] = {0, 0, 0, 0};
    int rq[4] = {0, 0, 0, 0};

    #pragma unroll
    for (int rr = 0; rr < RR; rr++) {
        xw[6] = sBits[rr + 2][lane];
        xw[7] = sBits[rr + 2][lane + 1];
        xw[8] = sBits[rr + 2][lane + 2];

        unsigned X012 = xor3(xw[0], xw[1], xw[2]);
        unsigned X345 = xor3(xw[3], xw[4], xw[5]);
        unsigned X678 = xor3(xw[6], xw[7], xw[8]);
        unsigned XAll = xor3(X012, X345, X678);

        int hv[4];
        #pragma unroll
        for (int j = 0; j < 4; j++) {
            int b = base[j];
            if (rr == 0 && top)      b += rctH[j];
            if (rr == RR - 1 && bot) b += rcbH[j];
            hv[j] = conv_ch_csa(xw, X012, X345, X678, XAll,
                                m[j], MR0[j], MR1[j], MR2[j], MAll[j], b);
            rs[j] += hv[j];
            rq[j] += hv[j] * hv[j];
        }

        *reinterpret_cast<char4*>(g_y2 + GY_IDX(n, h0 + rr, g, w)) =
            make_char4((signed char)hv[0], (signed char)hv[1],
                       (signed char)hv[2], (signed char)hv[3]);

        xw[0] = xw[3]; xw[1] = xw[4]; xw[2] = xw[5];
        xw[3] = xw[6]; xw[4] = xw[7]; xw[5] = xw[8];
    }

    #pragma unroll
    for (int j = 0; j < 4; j++) {
        int s = __reduce_add_sync(0xffffffffu, rs[j]);
        int q = __reduce_add_sync(0xffffffffu, rq[j]);
        if (lane == 0) {
            atomicAdd((unsigned long long*)&g_sum2[cb + j], (unsigned long long)(long long)s);
            atomicAdd((unsigned long long*)&g_ssq2[cb + j], (unsigned long long)(long long)q);
        }
    }
}

// ---------------- K4: out = x + a2*(2*yh2) + c2 (4 px/thread) -------------------
__global__ __launch_bounds__(256) void k_final(const float* __restrict__ x,
                                               const float* __restrict__ gamma,
                                               const float* __restrict__ beta,
                                               float* __restrict__ out) {
    __shared__ float sa[32], sc[32];
    int o = threadIdx.x;
    if (o < 32) {
        double mean = 2.0 * (double)g_sum2[o] / (double)NHW;
        double var  = 4.0 * (double)g_ssq2[o] / (double)NHW - mean * mean;
        double inv  = rsqrt(var + 1e-5);
        double a    = (double)gamma[o] * inv;
        sa[o] = (float)(2.0 * a);
        sc[o] = (float)((double)beta[o] - mean * a);
    }
    __syncthreads();

    int t = blockIdx.x * 256 + threadIdx.x;       // NHW/4 threads
    size_t p0 = (size_t)t * 4;
    int n = (int)(p0 / HW);
    int q = (int)(p0 % HW);
    int h = q / WW, w = q % WW;                   // w % 4 == 0

    #pragma unroll
    for (int g = 0; g < 8; g++) {
        union { uint4 u; signed char s[16]; } A;  // signed char: aarch64 plain char is unsigned
        A.u = *reinterpret_cast<const uint4*>(g_y2 + GY_IDX(n, h, g, w));
        #pragma unroll
        for (int j = 0; j < 4; j++) {
            int c = g * 4 + j;
            float a = sa[c], cc = sc[c];
            size_t xi = (size_t)(n * 32 + c) * HW + q;
            float4 xv = *reinterpret_cast<const float4*>(x + xi);
            float4 o4;
            o4.x = xv.x + fmaf(a, (float)A.s[0 + j],  cc);
            o4.y = xv.y + fmaf(a, (float)A.s[4 + j],  cc);
            o4.z = xv.z + fmaf(a, (float)A.s[8 + j],  cc);
            o4.w = xv.w + fmaf(a, (float)A.s[12 + j], cc);
            *reinterpret_cast<float4*>(out + xi) = o4;
        }
    }
}

// ---------------- launch ----------------
extern "C" void kernel_launch(void* const* d_in, const int* in_sizes, int n_in,
                              void* d_out, int out_size) {
    const float* x  = (const float*)d_in[0];
    const float* w1 = (const float*)d_in[1];
    const float* g1 = (const float*)d_in[2];
    const float* b1 = (const float*)d_in[3];
    const float* w2 = (const float*)d_in[4];
    const float* g2 = (const float*)d_in[5];
    const float* b2 = (const float*)d_in[6];
    float* out = (float*)d_out;

    k_prep<<<15, 1024>>>(w1, w2);
    k_pack_x<<<NHW / 4 / 256, 256>>>(x);
    k_conv1<<<NN * 7 * (HH / RR), dim3(32, 8)>>>();
    k_conv2p<<<NN * 7 * (HH / RR), dim3(32, 8)>>>(g1, b1);
    k_final<<<NHW / 4 / 256, 256>>>(x, g2, b2, out);
}

// round 12
// speedup vs baseline: 1.0508x; 1.0508x over previous
#include <cuda_runtime.h>
#include <cstdint>

#define NN 16
#define CC 32
#define HH 224
#define WW 224
#define HW (HH * WW)            // 50176
#define NHW (NN * HW)           // 802816
#define PW 226
#define PH 226
#define PHW (PW * PH)           // 51076
#define NPHW (NN * PHW)         // 817216
#define RR 16                   // rows per conv block (224/16 = 14 row-blocks)

// g_y layout: [n][h][group(8)][w][4ch] int8 (halved conv values).
#define GY_IDX(n, h, g, w) (((((size_t)(n) * HH + (h)) * 8 + (g)) * WW + (w)) * 4)

// ---------------- CSA helpers (single-LOP3 xor3 / majority) ----------------
__device__ __forceinline__ unsigned xor3(unsigned a, unsigned b, unsigned c) {
    unsigned r;
    asm("lop3.b32 %0, %1, %2, %3, 0x96;" : "=r"(r) : "r"(a), "r"(b), "r"(c));
    return r;
}
__device__ __forceinline__ unsigned maj3(unsigned a, unsigned b, unsigned c) {
    unsigned r;
    asm("lop3.b32 %0, %1, %2, %3, 0xE8;" : "=r"(r) : "r"(a), "r"(b), "r"(c));
    return r;
}

// ---------------- device scratch ----------------
__device__ unsigned    g_bits[NPHW];            // layer-1 input bits (padded)
__device__ signed char g_y[(size_t)NHW * 32];   // conv1 halved output (25.7 MB)
__device__ signed char g_y2[(size_t)NHW * 32];  // conv2 halved output (25.7 MB)
__device__ long long g_sum1[32], g_ssq1[32];    // stats of HALVED values
__device__ long long g_sum2[32], g_ssq2[32];
__device__ unsigned  g_wm0[288];
__device__ unsigned  g_wm1[288];

// ---------------- K0: zero BORDERS of padded bit image + masks + stats ----------
__global__ void k_prep(const float* __restrict__ w1, const float* __restrict__ w2) {
    int i = blockIdx.x * blockDim.x + threadIdx.x;
    if (i < NN * 900) {
        int img = i / 900, r = i % 900;
        int h, w;
        if (r < 226)      { h = 0;            w = r; }
        else if (r < 452) { h = 225;          w = r - 226; }
        else if (r < 676) { h = r - 452 + 1;  w = 0; }
        else              { h = r - 676 + 1;  w = 225; }
        g_bits[(size_t)img * PHW + (size_t)h * PW + w] = 0u;
    }
    if (blockIdx.x == 0) {
        int tid = threadIdx.x;
        if (tid < 288) {
            int o = tid / 9, t = tid % 9;
            unsigned m = 0;
            #pragma unroll
            for (int k = 0; k < 32; k++)
                m |= (w1[(o * 32 + k) * 9 + t] > 0.0f ? 1u : 0u) << k;
            g_wm0[tid] = m;
        } else if (tid < 576) {
            int j = tid - 288;
            int o = j / 9, t = j % 9;
            unsigned m = 0;
            #pragma unroll
            for (int k = 0; k < 32; k++)
                m |= (w2[(o * 32 + k) * 9 + t] > 0.0f ? 1u : 0u) << k;
            g_wm1[j] = m;
        } else if (tid < 608) {
            int o = tid - 576;
            g_sum1[o] = 0; g_ssq1[o] = 0;
            g_sum2[o] = 0; g_ssq2[o] = 0;
        }
    }
}

// ---------------- K1: binarize x -> packed bits ----------------
__global__ __launch_bounds__(256) void k_pack_x(const float* __restrict__ x) {
    int t = blockIdx.x * 256 + threadIdx.x;
    size_t p0 = (size_t)t * 4;
    int n = (int)(p0 / HW);
    int q = (int)(p0 % HW);
    unsigned b0 = 0, b1 = 0, b2 = 0, b3 = 0;
    #pragma unroll
    for (int c = 0; c < 32; c++) {
        const float4 v = *reinterpret_cast<const float4*>(x + ((size_t)(n * 32 + c) * HW + q));
        b0 |= (v.x > 0.0f ? 1u : 0u) << c;
        b1 |= (v.y > 0.0f ? 1u : 0u) << c;
        b2 |= (v.z > 0.0f ? 1u : 0u) << c;
        b3 |= (v.w > 0.0f ? 1u : 0u) << c;
    }
    int h = q / WW, w = q % WW;
    unsigned* d = g_bits + (size_t)n * PHW + (size_t)(h + 1) * PW + (w + 1);
    d[0] = b0; d[1] = b1; d[2] = b2; d[3] = b3;
}

// Per-channel CSA conv step (9->4 popc compressor, masks folded).
__device__ __forceinline__ int conv_ch_csa(
    const unsigned xw[9], unsigned XA, unsigned XB, unsigned XC, unsigned XAll,
    const unsigned m[9], unsigned MR0, unsigned MR1, unsigned MR2, unsigned MAll,
    int base) {
    unsigned c1 = maj3(xw[0] ^ m[0], xw[1] ^ m[1], xw[2] ^ m[2]);
    unsigned c2 = maj3(xw[3] ^ m[3], xw[4] ^ m[4], xw[5] ^ m[5]);
    unsigned c3 = maj3(xw[6] ^ m[6], xw[7] ^ m[7], xw[8] ^ m[8]);
    unsigned s1 = XA ^ MR0;
    unsigned s2 = XB ^ MR1;
    unsigned s3 = XC ^ MR2;
    unsigned s4 = XAll ^ MAll;
    unsigned c4 = maj3(s1, s2, s3);
    unsigned s5 = xor3(c1, c2, c3);
    unsigned c5 = maj3(c1, c2, c3);
    int cnt = __popc(s4) + ((__popc(c4) + __popc(s5)) << 1) + (__popc(c5) << 2);
    return base - cnt;      // base = 144 + half-corrections
}

// ---------------- K2: conv layer 1 — CSA core, 2 channels/warp, X-rotation ------
__global__ __launch_bounds__(512, 2) void k_conv1() {
    int bid   = blockIdx.x;
    int n     = bid / 98;                 // 7 strips * 14 rowblocks
    int rem   = bid % 98;
    int strip = rem % 7;
    int rb    = rem / 7;
    int w0    = strip * 32;
    int h0    = rb * RR;
    int lane  = threadIdx.x;
    int cb    = threadIdx.y * 2;          // 16 warps * 2 channels

    unsigned m[2][9], MR0[2], MR1[2], MR2[2], MAll[2];
    #pragma unroll
    for (int j = 0; j < 2; j++) {
        #pragma unroll
        for (int t = 0; t < 9; t++)
            m[j][t] = g_wm0[(cb + j) * 9 + t];
        MR0[j] = xor3(m[j][0], m[j][1], m[j][2]);
        MR1[j] = xor3(m[j][3], m[j][4], m[j][5]);
        MR2[j] = xor3(m[j][6], m[j][7], m[j][8]);
        MAll[j] = xor3(MR0[j], MR1[j], MR2[j]);
    }

    int w = w0 + lane;
    bool eL = (w == 0), eR = (w == WW - 1);

    int base[2], rctH[2], rcbH[2];
    #pragma unroll
    for (int j = 0; j < 2; j++) {
        int ch[9];
        #pragma unroll
        for (int t = 0; t < 9; t++) ch[t] = 16 - __popc(m[j][t]);   // half-corrections
        int caddH = eL ? -(ch[0] + ch[3] + ch[6]) : (eR ? -(ch[2] + ch[5] + ch[8]) : 0);
        base[j] = 144 + caddH;
        rctH[j] = -(ch[0] + ch[1] + ch[2]) + (eL ? ch[0] : 0) + (eR ? ch[2] : 0);
        rcbH[j] = -(ch[6] + ch[7] + ch[8]) + (eL ? ch[6] : 0) + (eR ? ch[8] : 0);
    }

    const unsigned* bp = g_bits + (size_t)n * PHW + (size_t)h0 * PW + w;
    unsigned xw[9];
    xw[0] = bp[0];  xw[1] = bp[1];      xw[2] = bp[2];
    xw[3] = bp[PW]; xw[4] = bp[PW + 1]; xw[5] = bp[PW + 2];
    unsigned XA = xor3(xw[0], xw[1], xw[2]);
    unsigned XB = xor3(xw[3], xw[4], xw[5]);

    bool top = (h0 == 0), bot = (h0 + RR == HH);
    int rs0 = 0, rs1 = 0, rq0 = 0, rq1 = 0;
    int gidx = cb >> 2;
    int goff = cb & 3;

    #pragma unroll
    for (int rr = 0; rr < RR; rr++) {
        const unsigned* qp = bp + (size_t)(rr + 2) * PW;
        xw[6] = qp[0]; xw[7] = qp[1]; xw[8] = qp[2];

        unsigned XC   = xor3(xw[6], xw[7], xw[8]);
        unsigned XAll = xor3(XA, XB, XC);

        int hv[2];
        #pragma unroll
        for (int j = 0; j < 2; j++) {
            int b = base[j];
            if (rr == 0 && top)      b += rctH[j];
            if (rr == RR - 1 && bot) b += rcbH[j];
            hv[j] = conv_ch_csa(xw, XA, XB, XC, XAll,
                                m[j], MR0[j], MR1[j], MR2[j], MAll[j], b);
        }
        rs0 += hv[0]; rq0 += hv[0] * hv[0];
        rs1 += hv[1]; rq1 += hv[1] * hv[1];

        *reinterpret_cast<short*>(g_y + GY_IDX(n, h0 + rr, gidx, w) + goff) =
            (short)(((unsigned short)(unsigned char)(signed char)hv[0]) |
                    ((unsigned short)(unsigned char)(signed char)hv[1] << 8));

        xw[0] = xw[3]; xw[1] = xw[4]; xw[2] = xw[5];
        xw[3] = xw[6]; xw[4] = xw[7]; xw[5] = xw[8];
        XA = XB; XB = XC;
    }

    int s0 = __reduce_add_sync(0xffffffffu, rs0);
    int q0 = __reduce_add_sync(0xffffffffu, rq0);
    int s1 = __reduce_add_sync(0xffffffffu, rs1);
    int q1 = __reduce_add_sync(0xffffffffu, rq1);
    if (lane == 0) {
        atomicAdd((unsigned long long*)&g_sum1[cb],     (unsigned long long)(long long)s0);
        atomicAdd((unsigned long long*)&g_ssq1[cb],     (unsigned long long)(long long)q0);
        atomicAdd((unsigned long long*)&g_sum1[cb + 1], (unsigned long long)(long long)s1);
        atomicAdd((unsigned long long*)&g_ssq1[cb + 1], (unsigned long long)(long long)q1);
    }
}

// ---------------- K3: FUSED threshold(conv1,BN1) + conv layer 2 (CSA) -----------
__global__ __launch_bounds__(512, 2) void k_conv2p(const float* __restrict__ gamma,
                                                   const float* __restrict__ beta) {
    __shared__ unsigned sBits[RR + 2][35];
    __shared__ int      sTc[32];
    __shared__ unsigned sFl[32];
    __shared__ unsigned sT[8], sF[8];

    int lane = threadIdx.x;
    int tid  = threadIdx.y * 32 + lane;

    int bid   = blockIdx.x;
    int n     = bid / 98;
    int rem   = bid % 98;
    int strip = rem % 7;
    int rb    = rem / 7;
    int w0    = strip * 32;
    int h0    = rb * RR;

    // ---- thresholds from exact integer stats of layer 1 ----
    if (tid < 32) {
        int o = tid;
        double mean = 2.0 * (double)g_sum1[o] / (double)NHW;
        double var  = 4.0 * (double)g_ssq1[o] / (double)NHW - mean * mean;
        double inv  = rsqrt(var + 1e-5);
        double a    = (double)gamma[o] * inv;
        double cst  = (double)beta[o] - mean * a;
        int T; unsigned f;
        if (a > 0.0)      { T = (int)floor(-cst / (2.0 * a));    f = 0x00u; }
        else if (a < 0.0) { T = (int)ceil(-cst / (2.0 * a)) - 1; f = 0xFFu; }
        else              { T = (cst > 0.0) ? -128 : 127;        f = 0x00u; }
        T = max(-128, min(127, T));
        sTc[o] = T & 0xFF;
        sFl[o] = f;
    }
    __syncthreads();
    if (tid < 8) {
        sT[tid] = (unsigned)sTc[4*tid] | ((unsigned)sTc[4*tid+1] << 8)
                | ((unsigned)sTc[4*tid+2] << 16) | ((unsigned)sTc[4*tid+3] << 24);
        sF[tid] = sFl[4*tid] | (sFl[4*tid+1] << 8) | (sFl[4*tid+2] << 16) | (sFl[4*tid+3] << 24);
    }
    __syncthreads();

    // ---- stage thresholded bits (halo tile) — R9-verified form ----
    for (int i = tid; i < (RR + 2) * 34; i += 512) {
        int hl = i / 34, wl = i % 34;
        int h = h0 - 1 + hl, w = w0 - 1 + wl;
        unsigned b = 0;
        if (h >= 0 && h < HH && w >= 0 && w < WW) {
            #pragma unroll
            for (int gg = 0; gg < 8; gg++) {
                unsigned A = *reinterpret_cast<const unsigned*>(g_y + GY_IDX(n, h, gg, w));
                unsigned mm = (__vcmpgts4(A, sT[gg]) ^ sF[gg]) & 0x01010101u;
                b |= ((unsigned)__dp4a(mm, 0x08040201u, 0u)) << (gg * 4);
            }
        }
        sBits[hl][wl] = b;
    }
    __syncthreads();

    // ---- conv from smem: CSA core, 2 channels/warp, X-rotation ----
    int cb = threadIdx.y * 2;
    unsigned m[2][9], MR0[2], MR1[2], MR2[2], MAll[2];
    #pragma unroll
    for (int j = 0; j < 2; j++) {
        #pragma unroll
        for (int t = 0; t < 9; t++)
            m[j][t] = g_wm1[(cb + j) * 9 + t];
        MR0[j] = xor3(m[j][0], m[j][1], m[j][2]);
        MR1[j] = xor3(m[j][3], m[j][4], m[j][5]);
        MR2[j] = xor3(m[j][6], m[j][7], m[j][8]);
        MAll[j] = xor3(MR0[j], MR1[j], MR2[j]);
    }

    int w = w0 + lane;
    bool eL = (w == 0), eR = (w == WW - 1);

    int base[2], rctH[2], rcbH[2];
    #pragma unroll
    for (int j = 0; j < 2; j++) {
        int ch[9];
        #pragma unroll
        for (int t = 0; t < 9; t++) ch[t] = 16 - __popc(m[j][t]);
        int caddH = eL ? -(ch[0] + ch[3] + ch[6]) : (eR ? -(ch[2] + ch[5] + ch[8]) : 0);
        base[j] = 144 + caddH;
        rctH[j] = -(ch[0] + ch[1] + ch[2]) + (eL ? ch[0] : 0) + (eR ? ch[2] : 0);
        rcbH[j] = -(ch[6] + ch[7] + ch[8]) + (eL ? ch[6] : 0) + (eR ? ch[8] : 0);
    }

    unsigned xw[9];
    xw[0] = sBits[0][lane]; xw[1] = sBits[0][lane + 1]; xw[2] = sBits[0][lane + 2];
    xw[3] = sBits[1][lane]; xw[4] = sBits[1][lane + 1]; xw[5] = sBits[1][lane + 2];
    unsigned XA = xor3(xw[0], xw[1], xw[2]);
    unsigned XB = xor3(xw[3], xw[4], xw[5]);

    bool top = (h0 == 0), bot = (h0 + RR == HH);
    int rs0 = 0, rs1 = 0, rq0 = 0, rq1 = 0;
    int gidx = cb >> 2;
    int goff = cb & 3;

    #pragma unroll
    for (int rr = 0; rr < RR; rr++) {
        xw[6] = sBits[rr + 2][lane];
        xw[7] = sBits[rr + 2][lane + 1];
        xw[8] = sBits[rr + 2][lane + 2];

        unsigned XC   = xor3(xw[6], xw[7], xw[8]);
        unsigned XAll = xor3(XA, XB, XC);

        int hv[2];
        #pragma unroll
        for (int j = 0; j < 2; j++) {
            int b = base[j];
            if (rr == 0 && top)      b += rctH[j];
            if (rr == RR - 1 && bot) b += rcbH[j];
            hv[j] = conv_ch_csa(xw, XA, XB, XC, XAll,
                                m[j], MR0[j], MR1[j], MR2[j], MAll[j], b);
        }
        rs0 += hv[0]; rq0 += hv[0] * hv[0];
        rs1 += hv[1]; rq1 += hv[1] * hv[1];

        *reinterpret_cast<short*>(g_y2 + GY_IDX(n, h0 + rr, gidx, w) + goff) =
            (short)(((unsigned short)(unsigned char)(signed char)hv[0]) |
                    ((unsigned short)(unsigned char)(signed char)hv[1] << 8));

        xw[0] = xw[3]; xw[1] = xw[4]; xw[2] = xw[5];
        xw[3] = xw[6]; xw[4] = xw[7]; xw[5] = xw[8];
        XA = XB; XB = XC;
    }

    int s0 = __reduce_add_sync(0xffffffffu, rs0);
    int q0 = __reduce_add_sync(0xffffffffu, rq0);
    int s1 = __reduce_add_sync(0xffffffffu, rs1);
    int q1 = __reduce_add_sync(0xffffffffu, rq1);
    if (lane == 0) {
        atomicAdd((unsigned long long*)&g_sum2[cb],     (unsigned long long)(long long)s0);
        atomicAdd((unsigned long long*)&g_ssq2[cb],     (unsigned long long)(long long)q0);
        atomicAdd((unsigned long long*)&g_sum2[cb + 1], (unsigned long long)(long long)s1);
        atomicAdd((unsigned long long*)&g_ssq2[cb + 1], (unsigned long long)(long long)q1);
    }
}

// ---------------- K4: out = x + a2*(2*yh2) + c2 (4 px/thread) -------------------
__global__ __launch_bounds__(256) void k_final(const float* __restrict__ x,
                                               const float* __restrict__ gamma,
                                               const float* __restrict__ beta,
                                               float* __restrict__ out) {
    __shared__ float sa[32], sc[32];
    int o = threadIdx.x;
    if (o < 32) {
        double mean = 2.0 * (double)g_sum2[o] / (double)NHW;
        double var  = 4.0 * (double)g_ssq2[o] / (double)NHW - mean * mean;
        double inv  = rsqrt(var + 1e-5);
        double a    = (double)gamma[o] * inv;
        sa[o] = (float)(2.0 * a);
        sc[o] = (float)((double)beta[o] - mean * a);
    }
    __syncthreads();

    int t = blockIdx.x * 256 + threadIdx.x;       // NHW/4 threads
    size_t p0 = (size_t)t * 4;
    int n = (int)(p0 / HW);
    int q = (int)(p0 % HW);
    int h = q / WW, w = q % WW;                   // w % 4 == 0

    #pragma unroll
    for (int g = 0; g < 8; g++) {
        union { uint4 u; signed char s[16]; } A;  // signed char: aarch64 plain char is unsigned
        A.u = *reinterpret_cast<const uint4*>(g_y2 + GY_IDX(n, h, g, w));
        #pragma unroll
        for (int j = 0; j < 4; j++) {
            int c = g * 4 + j;
            float a = sa[c], cc = sc[c];
            size_t xi = (size_t)(n * 32 + c) * HW + q;
            float4 xv = *reinterpret_cast<const float4*>(x + xi);
            float4 o4;
            o4.x = xv.x + fmaf(a, (float)A.s[0 + j],  cc);
            o4.y = xv.y + fmaf(a, (float)A.s[4 + j],  cc);
            o4.z = xv.z + fmaf(a, (float)A.s[8 + j],  cc);
            o4.w = xv.w + fmaf(a, (float)A.s[12 + j], cc);
            *reinterpret_cast<float4*>(out + xi) = o4;
        }
    }
}

// ---------------- launch ----------------
extern "C" void kernel_launch(void* const* d_in, const int* in_sizes, int n_in,
                              void* d_out, int out_size) {
    const float* x  = (const float*)d_in[0];
    const float* w1 = (const float*)d_in[1];
    const float* g1 = (const float*)d_in[2];
    const float* b1 = (const float*)d_in[3];
    const float* w2 = (const float*)d_in[4];
    const float* g2 = (const float*)d_in[5];
    const float* b2 = (const float*)d_in[6];
    float* out = (float*)d_out;

    k_prep<<<15, 1024>>>(w1, w2);
    k_pack_x<<<NHW / 4 / 256, 256>>>(x);
    k_conv1<<<NN * 7 * (HH / RR), dim3(32, 16)>>>();
    k_conv2p<<<NN * 7 * (HH / RR), dim3(32, 16)>>>(g1, b1);
    k_final<<<NHW / 4 / 256, 256>>>(x, g2, b2, out);
}

// round 14
// speedup vs baseline: 1.1618x; 1.1057x over previous
#include <cuda_runtime.h>
#include <cstdint>

#define NN 16
#define CC 32
#define HH 224
#define WW 224
#define HW (HH * WW)            // 50176
#define NHW (NN * HW)           // 802816
#define PW 226
#define PH 226
#define PHW (PW * PH)           // 51076
#define NPHW (NN * PHW)         // 817216
#define RR 28                   // rows per conv block (224/28 = 8 row-blocks)

// g_y layout: [n][h][group(8)][w][4ch] int8 (halved conv values).
#define GY_IDX(n, h, g, w) (((((size_t)(n) * HH + (h)) * 8 + (g)) * WW + (w)) * 4)

// ---------------- CSA helpers (single-LOP3 xor3 / majority) ----------------
__device__ __forceinline__ unsigned xor3(unsigned a, unsigned b, unsigned c) {
    unsigned r;
    asm("lop3.b32 %0, %1, %2, %3, 0x96;" : "=r"(r) : "r"(a), "r"(b), "r"(c));
    return r;
}
__device__ __forceinline__ unsigned maj3(unsigned a, unsigned b, unsigned c) {
    unsigned r;
    asm("lop3.b32 %0, %1, %2, %3, 0xE8;" : "=r"(r) : "r"(a), "r"(b), "r"(c));
    return r;
}

// ---------------- device scratch ----------------
__device__ unsigned    g_bits[NPHW];            // layer-1 input bits (padded)
__device__ signed char g_y[(size_t)NHW * 32];   // conv1 halved output (25.7 MB)
__device__ signed char g_y2[(size_t)NHW * 32];  // conv2 halved output (25.7 MB)
__device__ long long g_sum1[32], g_ssq1[32];    // stats of HALVED values
__device__ long long g_sum2[32], g_ssq2[32];
__device__ unsigned  g_wm0[288];
__device__ unsigned  g_wm1[288];

// ---------------- K1: binarize x -> packed bits + MERGED PREP -------------------
// Main work: 4 px/thread sign-packing (784 blocks cover NHW exactly).
// Designated blocks additionally zero the padded border, pack weight sign masks
// (STRIDED loop: 288 entries > 256 threads — this was the R11/R13 bug), and zero
// stats. Prep writes are disjoint from packing writes; consumed by later launches.
__global__ __launch_bounds__(256) void k_pack_x(const float* __restrict__ x,
                                                const float* __restrict__ w1,
                                                const float* __restrict__ w2) {
    int tid = threadIdx.x;
    int bid = blockIdx.x;
    int t = bid * 256 + tid;
    size_t p0 = (size_t)t * 4;
    int n = (int)(p0 / HW);
    int q = (int)(p0 % HW);
    unsigned b0 = 0, b1 = 0, b2 = 0, b3 = 0;
    #pragma unroll
    for (int c = 0; c < 32; c++) {
        const float4 v = *reinterpret_cast<const float4*>(x + ((size_t)(n * 32 + c) * HW + q));
        b0 |= (v.x > 0.0f ? 1u : 0u) << c;
        b1 |= (v.y > 0.0f ? 1u : 0u) << c;
        b2 |= (v.z > 0.0f ? 1u : 0u) << c;
        b3 |= (v.w > 0.0f ? 1u : 0u) << c;
    }
    int h = q / WW, w = q % WW;
    unsigned* d = g_bits + (size_t)n * PHW + (size_t)(h + 1) * PW + (w + 1);
    d[0] = b0; d[1] = b1; d[2] = b2; d[3] = b3;

    // ---- merged prep ----
    if (bid < 57) {                       // border zeroing: 16*900 = 14400 cells
        int i = bid * 256 + tid;
        if (i < NN * 900) {
            int img = i / 900, r = i % 900;
            int hh, ww;
            if (r < 226)      { hh = 0;            ww = r; }
            else if (r < 452) { hh = 225;          ww = r - 226; }
            else if (r < 676) { hh = r - 452 + 1;  ww = 0; }
            else              { hh = r - 676 + 1;  ww = 225; }
            g_bits[(size_t)img * PHW + (size_t)hh * PW + ww] = 0u;
        }
    } else if (bid == 57) {
        for (int i = tid; i < 288; i += 256) {    // FIX: 288 entries, 256 threads
            int o = i / 9, tt = i % 9;
            unsigned m = 0;
            #pragma unroll
            for (int k = 0; k < 32; k++)
                m |= (w1[(o * 32 + k) * 9 + tt] > 0.0f ? 1u : 0u) << k;
            g_wm0[i] = m;
        }
    } else if (bid == 58) {
        for (int i = tid; i < 288; i += 256) {    // FIX: 288 entries, 256 threads
            int o = i / 9, tt = i % 9;
            unsigned m = 0;
            #pragma unroll
            for (int k = 0; k < 32; k++)
                m |= (w2[(o * 32 + k) * 9 + tt] > 0.0f ? 1u : 0u) << k;
            g_wm1[i] = m;
        }
    } else if (bid == 59) {
        if (tid < 32) {
            g_sum1[tid] = 0; g_ssq1[tid] = 0;
            g_sum2[tid] = 0; g_ssq2[tid] = 0;
        }
    }
}

// Per-channel CSA conv step (9->4 popc compressor, masks folded).
__device__ __forceinline__ int conv_ch_csa(
    const unsigned xw[9], unsigned XA, unsigned XB, unsigned XC, unsigned XAll,
    const unsigned m[9], unsigned MR0, unsigned MR1, unsigned MR2, unsigned MAll,
    int base) {
    unsigned c1 = maj3(xw[0] ^ m[0], xw[1] ^ m[1], xw[2] ^ m[2]);
    unsigned c2 = maj3(xw[3] ^ m[3], xw[4] ^ m[4], xw[5] ^ m[5]);
    unsigned c3 = maj3(xw[6] ^ m[6], xw[7] ^ m[7], xw[8] ^ m[8]);
    unsigned s1 = XA ^ MR0;
    unsigned s2 = XB ^ MR1;
    unsigned s3 = XC ^ MR2;
    unsigned s4 = XAll ^ MAll;
    unsigned c4 = maj3(s1, s2, s3);
    unsigned s5 = xor3(c1, c2, c3);
    unsigned c5 = maj3(c1, c2, c3);
    int cnt = __popc(s4) + ((__popc(c4) + __popc(s5)) << 1) + (__popc(c5) << 2);
    return base - cnt;      // base = 144 + half-corrections
}

// ---------------- K2: conv layer 1 — CSA core, 2 channels/warp, X-rotation ------
__global__ __launch_bounds__(512, 2) void k_conv1() {
    int bid   = blockIdx.x;
    int n     = bid / 56;                 // 7 strips * 8 rowblocks
    int rem   = bid % 56;
    int strip = rem % 7;
    int rb    = rem / 7;
    int w0    = strip * 32;
    int h0    = rb * RR;
    int lane  = threadIdx.x;
    int cb    = threadIdx.y * 2;          // 16 warps * 2 channels

    unsigned m[2][9], MR0[2], MR1[2], MR2[2], MAll[2];
    #pragma unroll
    for (int j = 0; j < 2; j++) {
        #pragma unroll
        for (int t = 0; t < 9; t++)
            m[j][t] = g_wm0[(cb + j) * 9 + t];
        MR0[j] = xor3(m[j][0], m[j][1], m[j][2]);
        MR1[j] = xor3(m[j][3], m[j][4], m[j][5]);
        MR2[j] = xor3(m[j][6], m[j][7], m[j][8]);
        MAll[j] = xor3(MR0[j], MR1[j], MR2[j]);
    }

    int w = w0 + lane;
    bool eL = (w == 0), eR = (w == WW - 1);

    int base[2], rctH[2], rcbH[2];
    #pragma unroll
    for (int j = 0; j < 2; j++) {
        int ch[9];
        #pragma unroll
        for (int t = 0; t < 9; t++) ch[t] = 16 - __popc(m[j][t]);   // half-corrections
        int caddH = eL ? -(ch[0] + ch[3] + ch[6]) : (eR ? -(ch[2] + ch[5] + ch[8]) : 0);
        base[j] = 144 + caddH;
        rctH[j] = -(ch[0] + ch[1] + ch[2]) + (eL ? ch[0] : 0) + (eR ? ch[2] : 0);
        rcbH[j] = -(ch[6] + ch[7] + ch[8]) + (eL ? ch[6] : 0) + (eR ? ch[8] : 0);
    }

    const unsigned* bp = g_bits + (size_t)n * PHW + (size_t)h0 * PW + w;
    unsigned xw[9];
    xw[0] = bp[0];  xw[1] = bp[1];      xw[2] = bp[2];
    xw[3] = bp[PW]; xw[4] = bp[PW + 1]; xw[5] = bp[PW + 2];
    unsigned XA = xor3(xw[0], xw[1], xw[2]);
    unsigned XB = xor3(xw[3], xw[4], xw[5]);

    bool top = (h0 == 0), bot = (h0 + RR == HH);
    int rs0 = 0, rs1 = 0, rq0 = 0, rq1 = 0;
    int gidx = cb >> 2;
    int goff = cb & 3;

    #pragma unroll
    for (int rr = 0; rr < RR; rr++) {
        const unsigned* qp = bp + (size_t)(rr + 2) * PW;
        xw[6] = qp[0]; xw[7] = qp[1]; xw[8] = qp[2];

        unsigned XC   = xor3(xw[6], xw[7], xw[8]);
        unsigned XAll = xor3(XA, XB, XC);

        int hv[2];
        #pragma unroll
        for (int j = 0; j < 2; j++) {
            int b = base[j];
            if (rr == 0 && top)      b += rctH[j];
            if (rr == RR - 1 && bot) b += rcbH[j];
            hv[j] = conv_ch_csa(xw, XA, XB, XC, XAll,
                                m[j], MR0[j], MR1[j], MR2[j], MAll[j], b);
        }
        rs0 += hv[0]; rq0 += hv[0] * hv[0];
        rs1 += hv[1]; rq1 += hv[1] * hv[1];

        *reinterpret_cast<short*>(g_y + GY_IDX(n, h0 + rr, gidx, w) + goff) =
            (short)(((unsigned short)(unsigned char)(signed char)hv[0]) |
                    ((unsigned short)(unsigned char)(signed char)hv[1] << 8));

        xw[0] = xw[3]; xw[1] = xw[4]; xw[2] = xw[5];
        xw[3] = xw[6]; xw[4] = xw[7]; xw[5] = xw[8];
        XA = XB; XB = XC;
    }

    int s0 = __reduce_add_sync(0xffffffffu, rs0);
    int q0 = __reduce_add_sync(0xffffffffu, rq0);
    int s1 = __reduce_add_sync(0xffffffffu, rs1);
    int q1 = __reduce_add_sync(0xffffffffu, rq1);
    if (lane == 0) {
        atomicAdd((unsigned long long*)&g_sum1[cb],     (unsigned long long)(long long)s0);
        atomicAdd((unsigned long long*)&g_ssq1[cb],     (unsigned long long)(long long)q0);
        atomicAdd((unsigned long long*)&g_sum1[cb + 1], (unsigned long long)(long long)s1);
        atomicAdd((unsigned long long*)&g_ssq1[cb + 1], (unsigned long long)(long long)q1);
    }
}

// ---------------- K3: FUSED threshold(conv1,BN1) + conv layer 2 (CSA) -----------
__global__ __launch_bounds__(512, 2) void k_conv2p(const float* __restrict__ gamma,
                                                   const float* __restrict__ beta) {
    __shared__ unsigned sBits[RR + 2][35];
    __shared__ int      sTc[32];
    __shared__ unsigned sFl[32];
    __shared__ unsigned sT[8], sF[8];

    int lane = threadIdx.x;
    int tid  = threadIdx.y * 32 + lane;

    int bid   = blockIdx.x;
    int n     = bid / 56;
    int rem   = bid % 56;
    int strip = rem % 7;
    int rb    = rem / 7;
    int w0    = strip * 32;
    int h0    = rb * RR;

    // ---- thresholds from exact integer stats of layer 1 ----
    if (tid < 32) {
        int o = tid;
        double mean = 2.0 * (double)g_sum1[o] / (double)NHW;
        double var  = 4.0 * (double)g_ssq1[o] / (double)NHW - mean * mean;
        double inv  = rsqrt(var + 1e-5);
        double a    = (double)gamma[o] * inv;
        double cst  = (double)beta[o] - mean * a;
        int T; unsigned f;
        if (a > 0.0)      { T = (int)floor(-cst / (2.0 * a));    f = 0x00u; }
        else if (a < 0.0) { T = (int)ceil(-cst / (2.0 * a)) - 1; f = 0xFFu; }
        else              { T = (cst > 0.0) ? -128 : 127;        f = 0x00u; }
        T = max(-128, min(127, T));
        sTc[o] = T & 0xFF;
        sFl[o] = f;
    }
    __syncthreads();
    if (tid < 8) {
        sT[tid] = (unsigned)sTc[4*tid] | ((unsigned)sTc[4*tid+1] << 8)
                | ((unsigned)sTc[4*tid+2] << 16) | ((unsigned)sTc[4*tid+3] << 24);
        sF[tid] = sFl[4*tid] | (sFl[4*tid+1] << 8) | (sFl[4*tid+2] << 16) | (sFl[4*tid+3] << 24);
    }
    __syncthreads();

    // ---- stage thresholded bits (halo tile) — R9-verified form ----
    for (int i = tid; i < (RR + 2) * 34; i += 512) {
        int hl = i / 34, wl = i % 34;
        int h = h0 - 1 + hl, w = w0 - 1 + wl;
        unsigned b = 0;
        if (h >= 0 && h < HH && w >= 0 && w < WW) {
            #pragma unroll
            for (int gg = 0; gg < 8; gg++) {
                unsigned A = *reinterpret_cast<const unsigned*>(g_y + GY_IDX(n, h, gg, w));
                unsigned mm = (__vcmpgts4(A, sT[gg]) ^ sF[gg]) & 0x01010101u;
                b |= ((unsigned)__dp4a(mm, 0x08040201u, 0u)) << (gg * 4);
            }
        }
        sBits[hl][wl] = b;
    }
    __syncthreads();

    // ---- conv from smem: CSA core, 2 channels/warp, X-rotation ----
    int cb = threadIdx.y * 2;
    unsigned m[2][9], MR0[2], MR1[2], MR2[2], MAll[2];
    #pragma unroll
    for (int j = 0; j < 2; j++) {
        #pragma unroll
        for (int t = 0; t < 9; t++)
            m[j][t] = g_wm1[(cb + j) * 9 + t];
        MR0[j] = xor3(m[j][0], m[j][1], m[j][2]);
        MR1[j] = xor3(m[j][3], m[j][4], m[j][5]);
        MR2[j] = xor3(m[j][6], m[j][7], m[j][8]);
        MAll[j] = xor3(MR0[j], MR1[j], MR2[j]);
    }

    int w = w0 + lane;
    bool eL = (w == 0), eR = (w == WW - 1);

    int base[2], rctH[2], rcbH[2];
    #pragma unroll
    for (int j = 0; j < 2; j++) {
        int ch[9];
        #pragma unroll
        for (int t = 0; t < 9; t++) ch[t] = 16 - __popc(m[j][t]);
        int caddH = eL ? -(ch[0] + ch[3] + ch[6]) : (eR ? -(ch[2] + ch[5] + ch[8]) : 0);
        base[j] = 144 + caddH;
        rctH[j] = -(ch[0] + ch[1] + ch[2]) + (eL ? ch[0] : 0) + (eR ? ch[2] : 0);
        rcbH[j] = -(ch[6] + ch[7] + ch[8]) + (eL ? ch[6] : 0) + (eR ? ch[8] : 0);
    }

    unsigned xw[9];
    xw[0] = sBits[0][lane]; xw[1] = sBits[0][lane + 1]; xw[2] = sBits[0][lane + 2];
    xw[3] = sBits[1][lane]; xw[4] = sBits[1][lane + 1]; xw[5] = sBits[1][lane + 2];
    unsigned XA = xor3(xw[0], xw[1], xw[2]);
    unsigned XB = xor3(xw[3], xw[4], xw[5]);

    bool top = (h0 == 0), bot = (h0 + RR == HH);
    int rs0 = 0, rs1 = 0, rq0 = 0, rq1 = 0;
    int gidx = cb >> 2;
    int goff = cb & 3;

    #pragma unroll
    for (int rr = 0; rr < RR; rr++) {
        xw[6] = sBits[rr + 2][lane];
        xw[7] = sBits[rr + 2][lane + 1];
        xw[8] = sBits[rr + 2][lane + 2];

        unsigned XC   = xor3(xw[6], xw[7], xw[8]);
        unsigned XAll = xor3(XA, XB, XC);

        int hv[2];
        #pragma unroll
        for (int j = 0; j < 2; j++) {
            int b = base[j];
            if (rr == 0 && top)      b += rctH[j];
            if (rr == RR - 1 && bot) b += rcbH[j];
            hv[j] = conv_ch_csa(xw, XA, XB, XC, XAll,
                                m[j], MR0[j], MR1[j], MR2[j], MAll[j], b);
        }
        rs0 += hv[0]; rq0 += hv[0] * hv[0];
        rs1 += hv[1]; rq1 += hv[1] * hv[1];

        *reinterpret_cast<short*>(g_y2 + GY_IDX(n, h0 + rr, gidx, w) + goff) =
            (short)(((unsigned short)(unsigned char)(signed char)hv[0]) |
                    ((unsigned short)(unsigned char)(signed char)hv[1] << 8));

        xw[0] = xw[3]; xw[1] = xw[4]; xw[2] = xw[5];
        xw[3] = xw[6]; xw[4] = xw[7]; xw[5] = xw[8];
        XA = XB; XB = XC;
    }

    int s0 = __reduce_add_sync(0xffffffffu, rs0);
    int q0 = __reduce_add_sync(0xffffffffu, rq0);
    int s1 = __reduce_add_sync(0xffffffffu, rs1);
    int q1 = __reduce_add_sync(0xffffffffu, rq1);
    if (lane == 0) {
        atomicAdd((unsigned long long*)&g_sum2[cb],     (unsigned long long)(long long)s0);
        atomicAdd((unsigned long long*)&g_ssq2[cb],     (unsigned long long)(long long)q0);
        atomicAdd((unsigned long long*)&g_sum2[cb + 1], (unsigned long long)(long long)s1);
        atomicAdd((unsigned long long*)&g_ssq2[cb + 1], (unsigned long long)(long long)q1);
    }
}

// ---------------- K4: out = x + a2*(2*yh2) + c2 (4 px/thread) -------------------
__global__ __launch_bounds__(256) void k_final(const float* __restrict__ x,
                                               const float* __restrict__ gamma,
                                               const float* __restrict__ beta,
                                               float* __restrict__ out) {
    __shared__ float sa[32], sc[32];
    int o = threadIdx.x;
    if (o < 32) {
        double mean = 2.0 * (double)g_sum2[o] / (double)NHW;
        double var  = 4.0 * (double)g_ssq2[o] / (double)NHW - mean * mean;
        double inv  = rsqrt(var + 1e-5);
        double a    = (double)gamma[o] * inv;
        sa[o] = (float)(2.0 * a);
        sc[o] = (float)((double)beta[o] - mean * a);
    }
    __syncthreads();

    int t = blockIdx.x * 256 + threadIdx.x;       // NHW/4 threads
    size_t p0 = (size_t)t * 4;
    int n = (int)(p0 / HW);
    int q = (int)(p0 % HW);
    int h = q / WW, w = q % WW;                   // w % 4 == 0

    #pragma unroll
    for (int g = 0; g < 8; g++) {
        union { uint4 u; signed char s[16]; } A;  // signed char: aarch64 plain char is unsigned
        A.u = *reinterpret_cast<const uint4*>(g_y2 + GY_IDX(n, h, g, w));
        #pragma unroll
        for (int j = 0; j < 4; j++) {
            int c = g * 4 + j;
            float a = sa[c], cc = sc[c];
            size_t xi = (size_t)(n * 32 + c) * HW + q;
            float4 xv = *reinterpret_cast<const float4*>(x + xi);
            float4 o4;
            o4.x = xv.x + fmaf(a, (float)A.s[0 + j],  cc);
            o4.y = xv.y + fmaf(a, (float)A.s[4 + j],  cc);
            o4.z = xv.z + fmaf(a, (float)A.s[8 + j],  cc);
            o4.w = xv.w + fmaf(a, (float)A.s[12 + j], cc);
            *reinterpret_cast<float4*>(out + xi) = o4;
        }
    }
}

// ---------------- launch ----------------
extern "C" void kernel_launch(void* const* d_in, const int* in_sizes, int n_in,
                              void* d_out, int out_size) {
    const float* x  = (const float*)d_in[0];
    const float* w1 = (const float*)d_in[1];
    const float* g1 = (const float*)d_in[2];
    const float* b1 = (const float*)d_in[3];
    const float* w2 = (const float*)d_in[4];
    const float* g2 = (const float*)d_in[5];
    const float* b2 = (const float*)d_in[6];
    float* out = (float*)d_out;

    k_pack_x<<<NHW / 4 / 256, 256>>>(x, w1, w2);
    k_conv1<<<NN * 7 * (HH / RR), dim3(32, 16)>>>();
    k_conv2p<<<NN * 7 * (HH / RR), dim3(32, 16)>>>(g1, b1);
    k_final<<<NHW / 4 / 256, 256>>>(x, g2, b2, out);
}

// round 15
// speedup vs baseline: 1.1690x; 1.0062x over previous
#include <cuda_runtime.h>
#include <cstdint>

#define NN 16
#define CC 32
#define HH 224
#define WW 224
#define HW (HH * WW)            // 50176
#define NHW (NN * HW)           // 802816
#define PW 226
#define PH 226
#define PHW (PW * PH)           // 51076
#define NPHW (NN * PHW)         // 817216
#define RR 28                   // rows per conv block (224/28 = 8 row-blocks)

// g_y layout: [n][h][group(8)][w][4ch] int8 (halved conv values).
#define GY_IDX(n, h, g, w) (((((size_t)(n) * HH + (h)) * 8 + (g)) * WW + (w)) * 4)

// ---------------- CSA helpers (single-LOP3 xor3 / majority) ----------------
__device__ __forceinline__ unsigned xor3(unsigned a, unsigned b, unsigned c) {
    unsigned r;
    asm("lop3.b32 %0, %1, %2, %3, 0x96;" : "=r"(r) : "r"(a), "r"(b), "r"(c));
    return r;
}
__device__ __forceinline__ unsigned maj3(unsigned a, unsigned b, unsigned c) {
    unsigned r;
    asm("lop3.b32 %0, %1, %2, %3, 0xE8;" : "=r"(r) : "r"(a), "r"(b), "r"(c));
    return r;
}

// ---------------- device scratch ----------------
__device__ unsigned    g_bits[NPHW];            // layer-1 input bits (padded)
__device__ signed char g_y[(size_t)NHW * 32];   // conv1 halved output (25.7 MB)
__device__ signed char g_y2[(size_t)NHW * 32];  // conv2 halved output (25.7 MB)
__device__ long long g_sum1[32], g_ssq1[32];    // stats of HALVED values
__device__ long long g_sum2[32], g_ssq2[32];
__device__ unsigned  g_wm0[288];
__device__ unsigned  g_wm1[288];

// ---------------- K1: binarize x -> packed bits + MERGED PREP -------------------
__global__ __launch_bounds__(256) void k_pack_x(const float* __restrict__ x,
                                                const float* __restrict__ w1,
                                                const float* __restrict__ w2) {
    int tid = threadIdx.x;
    int bid = blockIdx.x;
    int t = bid * 256 + tid;
    size_t p0 = (size_t)t * 4;
    int n = (int)(p0 / HW);
    int q = (int)(p0 % HW);
    unsigned b0 = 0, b1 = 0, b2 = 0, b3 = 0;
    #pragma unroll
    for (int c = 0; c < 32; c++) {
        const float4 v = *reinterpret_cast<const float4*>(x + ((size_t)(n * 32 + c) * HW + q));
        b0 |= (v.x > 0.0f ? 1u : 0u) << c;
        b1 |= (v.y > 0.0f ? 1u : 0u) << c;
        b2 |= (v.z > 0.0f ? 1u : 0u) << c;
        b3 |= (v.w > 0.0f ? 1u : 0u) << c;
    }
    int h = q / WW, w = q % WW;
    unsigned* d = g_bits + (size_t)n * PHW + (size_t)(h + 1) * PW + (w + 1);
    d[0] = b0; d[1] = b1; d[2] = b2; d[3] = b3;

    // ---- merged prep ----
    if (bid < 57) {                       // border zeroing: 16*900 = 14400 cells
        int i = bid * 256 + tid;
        if (i < NN * 900) {
            int img = i / 900, r = i % 900;
            int hh, ww;
            if (r < 226)      { hh = 0;            ww = r; }
            else if (r < 452) { hh = 225;          ww = r - 226; }
            else if (r < 676) { hh = r - 452 + 1;  ww = 0; }
            else              { hh = r - 676 + 1;  ww = 225; }
            g_bits[(size_t)img * PHW + (size_t)hh * PW + ww] = 0u;
        }
    } else if (bid == 57) {
        for (int i = tid; i < 288; i += 256) {    // strided: 288 entries, 256 threads
            int o = i / 9, tt = i % 9;
            unsigned m = 0;
            #pragma unroll
            for (int k = 0; k < 32; k++)
                m |= (w1[(o * 32 + k) * 9 + tt] > 0.0f ? 1u : 0u) << k;
            g_wm0[i] = m;
        }
    } else if (bid == 58) {
        for (int i = tid; i < 288; i += 256) {
            int o = i / 9, tt = i % 9;
            unsigned m = 0;
            #pragma unroll
            for (int k = 0; k < 32; k++)
                m |= (w2[(o * 32 + k) * 9 + tt] > 0.0f ? 1u : 0u) << k;
            g_wm1[i] = m;
        }
    } else if (bid == 59) {
        if (tid < 32) {
            g_sum1[tid] = 0; g_ssq1[tid] = 0;
            g_sum2[tid] = 0; g_ssq2[tid] = 0;
        }
    }
}

// Per-channel CSA conv step (9->4 popc compressor, masks folded).
__device__ __forceinline__ int conv_ch_csa(
    const unsigned xw[9], unsigned XA, unsigned XB, unsigned XC, unsigned XAll,
    const unsigned m[9], unsigned MR0, unsigned MR1, unsigned MR2, unsigned MAll,
    int base) {
    unsigned c1 = maj3(xw[0] ^ m[0], xw[1] ^ m[1], xw[2] ^ m[2]);
    unsigned c2 = maj3(xw[3] ^ m[3], xw[4] ^ m[4], xw[5] ^ m[5]);
    unsigned c3 = maj3(xw[6] ^ m[6], xw[7] ^ m[7], xw[8] ^ m[8]);
    unsigned s1 = XA ^ MR0;
    unsigned s2 = XB ^ MR1;
    unsigned s3 = XC ^ MR2;
    unsigned s4 = XAll ^ MAll;
    unsigned c4 = maj3(s1, s2, s3);
    unsigned s5 = xor3(c1, c2, c3);
    unsigned c5 = maj3(c1, c2, c3);
    int cnt = __popc(s4) + ((__popc(c4) + __popc(s5)) << 1) + (__popc(c5) << 2);
    return base - cnt;      // base = 144 + half-corrections
}

// ---------------- K2: conv layer 1 — CSA core, 2 channels/warp, X-rotation ------
__global__ __launch_bounds__(512, 2) void k_conv1() {
    int bid   = blockIdx.x;
    int n     = bid / 56;                 // 7 strips * 8 rowblocks
    int rem   = bid % 56;
    int strip = rem % 7;
    int rb    = rem / 7;
    int w0    = strip * 32;
    int h0    = rb * RR;
    int lane  = threadIdx.x;
    int cb    = threadIdx.y * 2;          // 16 warps * 2 channels

    unsigned m[2][9], MR0[2], MR1[2], MR2[2], MAll[2];
    #pragma unroll
    for (int j = 0; j < 2; j++) {
        #pragma unroll
        for (int t = 0; t < 9; t++)
            m[j][t] = g_wm0[(cb + j) * 9 + t];
        MR0[j] = xor3(m[j][0], m[j][1], m[j][2]);
        MR1[j] = xor3(m[j][3], m[j][4], m[j][5]);
        MR2[j] = xor3(m[j][6], m[j][7], m[j][8]);
        MAll[j] = xor3(MR0[j], MR1[j], MR2[j]);
    }

    int w = w0 + lane;
    bool eL = (w == 0), eR = (w == WW - 1);

    int base[2], rctH[2], rcbH[2];
    #pragma unroll
    for (int j = 0; j < 2; j++) {
        int ch[9];
        #pragma unroll
        for (int t = 0; t < 9; t++) ch[t] = 16 - __popc(m[j][t]);   // half-corrections
        int caddH = eL ? -(ch[0] + ch[3] + ch[6]) : (eR ? -(ch[2] + ch[5] + ch[8]) : 0);
        base[j] = 144 + caddH;
        rctH[j] = -(ch[0] + ch[1] + ch[2]) + (eL ? ch[0] : 0) + (eR ? ch[2] : 0);
        rcbH[j] = -(ch[6] + ch[7] + ch[8]) + (eL ? ch[6] : 0) + (eR ? ch[8] : 0);
    }

    const unsigned* bp = g_bits + (size_t)n * PHW + (size_t)h0 * PW + w;
    unsigned xw[9];
    xw[0] = bp[0];  xw[1] = bp[1];      xw[2] = bp[2];
    xw[3] = bp[PW]; xw[4] = bp[PW + 1]; xw[5] = bp[PW + 2];
    unsigned XA = xor3(xw[0], xw[1], xw[2]);
    unsigned XB = xor3(xw[3], xw[4], xw[5]);

    bool top = (h0 == 0), bot = (h0 + RR == HH);
    int rs0 = 0, rs1 = 0, rq0 = 0, rq1 = 0;
    int gidx = cb >> 2;
    int goff = cb & 3;

    #pragma unroll
    for (int rr = 0; rr < RR; rr++) {
        const unsigned* qp = bp + (size_t)(rr + 2) * PW;
        xw[6] = qp[0]; xw[7] = qp[1]; xw[8] = qp[2];

        unsigned XC   = xor3(xw[6], xw[7], xw[8]);
        unsigned XAll = xor3(XA, XB, XC);

        int hv[2];
        #pragma unroll
        for (int j = 0; j < 2; j++) {
            int b = base[j];
            if (rr == 0 && top)      b += rctH[j];
            if (rr == RR - 1 && bot) b += rcbH[j];
            hv[j] = conv_ch_csa(xw, XA, XB, XC, XAll,
                                m[j], MR0[j], MR1[j], MR2[j], MAll[j], b);
        }
        rs0 += hv[0]; rq0 += hv[0] * hv[0];
        rs1 += hv[1]; rq1 += hv[1] * hv[1];

        *reinterpret_cast<short*>(g_y + GY_IDX(n, h0 + rr, gidx, w) + goff) =
            (short)(((unsigned short)(unsigned char)(signed char)hv[0]) |
                    ((unsigned short)(unsigned char)(signed char)hv[1] << 8));

        xw[0] = xw[3]; xw[1] = xw[4]; xw[2] = xw[5];
        xw[3] = xw[6]; xw[4] = xw[7]; xw[5] = xw[8];
        XA = XB; XB = XC;
    }

    int s0 = __reduce_add_sync(0xffffffffu, rs0);
    int q0 = __reduce_add_sync(0xffffffffu, rq0);
    int s1 = __reduce_add_sync(0xffffffffu, rs1);
    int q1 = __reduce_add_sync(0xffffffffu, rq1);
    if (lane == 0) {
        atomicAdd((unsigned long long*)&g_sum1[cb],     (unsigned long long)(long long)s0);
        atomicAdd((unsigned long long*)&g_ssq1[cb],     (unsigned long long)(long long)q0);
        atomicAdd((unsigned long long*)&g_sum1[cb + 1], (unsigned long long)(long long)s1);
        atomicAdd((unsigned long long*)&g_ssq1[cb + 1], (unsigned long long)(long long)q1);
    }
}

// ---------------- K3: FUSED threshold(conv1,BN1) + conv layer 2 (CSA) -----------
__global__ __launch_bounds__(512, 2) void k_conv2p(const float* __restrict__ gamma,
                                                   const float* __restrict__ beta) {
    __shared__ unsigned sBits[RR + 2][35];
    __shared__ int      sTc[32];
    __shared__ unsigned sFl[32];
    __shared__ unsigned sT[8], sF[8];

    int lane = threadIdx.x;
    int tid  = threadIdx.y * 32 + lane;

    int bid   = blockIdx.x;
    int n     = bid / 56;
    int rem   = bid % 56;
    int strip = rem % 7;
    int rb    = rem / 7;
    int w0    = strip * 32;
    int h0    = rb * RR;

    // ---- thresholds from exact integer stats of layer 1 ----
    if (tid < 32) {
        int o = tid;
        double mean = 2.0 * (double)g_sum1[o] / (double)NHW;
        double var  = 4.0 * (double)g_ssq1[o] / (double)NHW - mean * mean;
        double inv  = rsqrt(var + 1e-5);
        double a    = (double)gamma[o] * inv;
        double cst  = (double)beta[o] - mean * a;
        int T; unsigned f;
        if (a > 0.0)      { T = (int)floor(-cst / (2.0 * a));    f = 0x00u; }
        else if (a < 0.0) { T = (int)ceil(-cst / (2.0 * a)) - 1; f = 0xFFu; }
        else              { T = (cst > 0.0) ? -128 : 127;        f = 0x00u; }
        T = max(-128, min(127, T));
        sTc[o] = T & 0xFF;
        sFl[o] = f;
    }
    __syncthreads();
    if (tid < 8) {
        sT[tid] = (unsigned)sTc[4*tid] | ((unsigned)sTc[4*tid+1] << 8)
                | ((unsigned)sTc[4*tid+2] << 16) | ((unsigned)sTc[4*tid+3] << 24);
        sF[tid] = sFl[4*tid] | (sFl[4*tid+1] << 8) | (sFl[4*tid+2] << 16) | (sFl[4*tid+3] << 24);
    }
    __syncthreads();

    // ---- stage thresholded bits (halo tile), dp4a-paired packing ----
    // channels 8p..8p+3 via weights 1,2,4,8; channels 8p+4..8p+7 via 0x10..0x80;
    // byte p of b = channels 8p..8p+7  =>  bit c of b = channel c.
    for (int i = tid; i < (RR + 2) * 34; i += 512) {
        int hl = i / 34, wl = i % 34;
        int h = h0 - 1 + hl, w = w0 - 1 + wl;
        unsigned b = 0;
        if ((unsigned)h < HH && (unsigned)w < WW) {
            const unsigned* gp = reinterpret_cast<const unsigned*>(g_y + GY_IDX(n, h, 0, w));
            unsigned p[4];
            #pragma unroll
            for (int pr = 0; pr < 4; pr++) {
                unsigned A0 = gp[(2 * pr)     * WW];
                unsigned A1 = gp[(2 * pr + 1) * WW];
                unsigned m0 = (__vcmpgts4(A0, sT[2*pr])     ^ sF[2*pr])     & 0x01010101u;
                unsigned m1 = (__vcmpgts4(A1, sT[2*pr + 1]) ^ sF[2*pr + 1]) & 0x01010101u;
                unsigned pv = __dp4a(m0, 0x08040201u, 0u);
                p[pr] = __dp4a(m1, 0x80402010u, pv);
            }
            b = p[0] | (p[1] << 8) | (p[2] << 16) | (p[3] << 24);
        }
        sBits[hl][wl] = b;
    }
    __syncthreads();

    // ---- conv from smem: CSA core, 2 channels/warp, X-rotation ----
    int cb = threadIdx.y * 2;
    unsigned m[2][9], MR0[2], MR1[2], MR2[2], MAll[2];
    #pragma unroll
    for (int j = 0; j < 2; j++) {
        #pragma unroll
        for (int t = 0; t < 9; t++)
            m[j][t] = g_wm1[(cb + j) * 9 + t];
        MR0[j] = xor3(m[j][0], m[j][1], m[j][2]);
        MR1[j] = xor3(m[j][3], m[j][4], m[j][5]);
        MR2[j] = xor3(m[j][6], m[j][7], m[j][8]);
        MAll[j] = xor3(MR0[j], MR1[j], MR2[j]);
    }

    int w = w0 + lane;
    bool eL = (w == 0), eR = (w == WW - 1);

    int base[2], rctH[2], rcbH[2];
    #pragma unroll
    for (int j = 0; j < 2; j++) {
        int ch[9];
        #pragma unroll
        for (int t = 0; t < 9; t++) ch[t] = 16 - __popc(m[j][t]);
        int caddH = eL ? -(ch[0] + ch[3] + ch[6]) : (eR ? -(ch[2] + ch[5] + ch[8]) : 0);
        base[j] = 144 + caddH;
        rctH[j] = -(ch[0] + ch[1] + ch[2]) + (eL ? ch[0] : 0) + (eR ? ch[2] : 0);
        rcbH[j] = -(ch[6] + ch[7] + ch[8]) + (eL ? ch[6] : 0) + (eR ? ch[8] : 0);
    }

    unsigned xw[9];
    xw[0] = sBits[0][lane]; xw[1] = sBits[0][lane + 1]; xw[2] = sBits[0][lane + 2];
    xw[3] = sBits[1][lane]; xw[4] = sBits[1][lane + 1]; xw[5] = sBits[1][lane + 2];
    unsigned XA = xor3(xw[0], xw[1], xw[2]);
    unsigned XB = xor3(xw[3], xw[4], xw[5]);

    bool top = (h0 == 0), bot = (h0 + RR == HH);
    int rs0 = 0, rs1 = 0, rq0 = 0, rq1 = 0;
    int gidx = cb >> 2;
    int goff = cb & 3;

    #pragma unroll
    for (int rr = 0; rr < RR; rr++) {
        xw[6] = sBits[rr + 2][lane];
        xw[7] = sBits[rr + 2][lane + 1];
        xw[8] = sBits[rr + 2][lane + 2];

        unsigned XC   = xor3(xw[6], xw[7], xw[8]);
        unsigned XAll = xor3(XA, XB, XC);

        int hv[2];
        #pragma unroll
        for (int j = 0; j < 2; j++) {
            int b = base[j];
            if (rr == 0 && top)      b += rctH[j];
            if (rr == RR - 1 && bot) b += rcbH[j];
            hv[j] = conv_ch_csa(xw, XA, XB, XC, XAll,
                                m[j], MR0[j], MR1[j], MR2[j], MAll[j], b);
        }
        rs0 += hv[0]; rq0 += hv[0] * hv[0];
        rs1 += hv[1]; rq1 += hv[1] * hv[1];

        *reinterpret_cast<short*>(g_y2 + GY_IDX(n, h0 + rr, gidx, w) + goff) =
            (short)(((unsigned short)(unsigned char)(signed char)hv[0]) |
                    ((unsigned short)(unsigned char)(signed char)hv[1] << 8));

        xw[0] = xw[3]; xw[1] = xw[4]; xw[2] = xw[5];
        xw[3] = xw[6]; xw[4] = xw[7]; xw[5] = xw[8];
        XA = XB; XB = XC;
    }

    int s0 = __reduce_add_sync(0xffffffffu, rs0);
    int q0 = __reduce_add_sync(0xffffffffu, rq0);
    int s1 = __reduce_add_sync(0xffffffffu, rs1);
    int q1 = __reduce_add_sync(0xffffffffu, rq1);
    if (lane == 0) {
        atomicAdd((unsigned long long*)&g_sum2[cb],     (unsigned long long)(long long)s0);
        atomicAdd((unsigned long long*)&g_ssq2[cb],     (unsigned long long)(long long)q0);
        atomicAdd((unsigned long long*)&g_sum2[cb + 1], (unsigned long long)(long long)s1);
        atomicAdd((unsigned long long*)&g_ssq2[cb + 1], (unsigned long long)(long long)q1);
    }
}

// ---------------- K4: out = x + a2*(2*yh2) + c2 (4 px/thread) -------------------
__global__ __launch_bounds__(256) void k_final(const float* __restrict__ x,
                                               const float* __restrict__ gamma,
                                               const float* __restrict__ beta,
                                               float* __restrict__ out) {
    __shared__ float sa[32], sc[32];
    int o = threadIdx.x;
    if (o < 32) {
        double mean = 2.0 * (double)g_sum2[o] / (double)NHW;
        double var  = 4.0 * (double)g_ssq2[o] / (double)NHW - mean * mean;
        double inv  = rsqrt(var + 1e-5);
        double a    = (double)gamma[o] * inv;
        sa[o] = (float)(2.0 * a);
        sc[o] = (float)((double)beta[o] - mean * a);
    }
    __syncthreads();

    int t = blockIdx.x * 256 + threadIdx.x;       // NHW/4 threads
    size_t p0 = (size_t)t * 4;
    int n = (int)(p0 / HW);
    int q = (int)(p0 % HW);
    int h = q / WW, w = q % WW;                   // w % 4 == 0

    #pragma unroll
    for (int g = 0; g < 8; g++) {
        union { uint4 u; signed char s[16]; } A;  // signed char: aarch64 plain char is unsigned
        A.u = *reinterpret_cast<const uint4*>(g_y2 + GY_IDX(n, h, g, w));
        #pragma unroll
        for (int j = 0; j < 4; j++) {
            int c = g * 4 + j;
            float a = sa[c], cc = sc[c];
            size_t xi = (size_t)(n * 32 + c) * HW + q;
            float4 xv = *reinterpret_cast<const float4*>(x + xi);
            float4 o4;
            o4.x = xv.x + fmaf(a, (float)A.s[0 + j],  cc);
            o4.y = xv.y + fmaf(a, (float)A.s[4 + j],  cc);
            o4.z = xv.z + fmaf(a, (float)A.s[8 + j],  cc);
            o4.w = xv.w + fmaf(a, (float)A.s[12 + j], cc);
            *reinterpret_cast<float4*>(out + xi) = o4;
        }
    }
}

// ---------------- launch ----------------
extern "C" void kernel_launch(void* const* d_in, const int* in_sizes, int n_in,
                              void* d_out, int out_size) {
    const float* x  = (const float*)d_in[0];
    const float* w1 = (const float*)d_in[1];
    const float* g1 = (const float*)d_in[2];
    const float* b1 = (const float*)d_in[3];
    const float* w2 = (const float*)d_in[4];
    const float* g2 = (const float*)d_in[5];
    const float* b2 = (const float*)d_in[6];
    float* out = (float*)d_out;

    k_pack_x<<<NHW / 4 / 256, 256>>>(x, w1, w2);
    k_conv1<<<NN * 7 * (HH / RR), dim3(32, 16)>>>();
    k_conv2p<<<NN * 7 * (HH / RR), dim3(32, 16)>>>(g1, b1);
    k_final<<<NHW / 4 / 256, 256>>>(x, g2, b2, out);
}

// round 16
// speedup vs baseline: 1.1751x; 1.0052x over previous
#include <cuda_runtime.h>
#include <cstdint>

#define NN 16
#define CC 32
#define HH 224
#define WW 224
#define HW (HH * WW)            // 50176
#define NHW (NN * HW)           // 802816
#define PW 226
#define PH 226
#define PHW (PW * PH)           // 51076
#define NPHW (NN * PHW)         // 817216
#define RR 28                   // rows per conv block (224/28 = 8 row-blocks)

// g_y layout: [n][h][group(8)][w][4ch] int8 (halved conv values).
#define GY_IDX(n, h, g, w) (((((size_t)(n) * HH + (h)) * 8 + (g)) * WW + (w)) * 4)

// ---------------- CSA helpers (single-LOP3 xor3 / majority) ----------------
__device__ __forceinline__ unsigned xor3(unsigned a, unsigned b, unsigned c) {
    unsigned r;
    asm("lop3.b32 %0, %1, %2, %3, 0x96;" : "=r"(r) : "r"(a), "r"(b), "r"(c));
    return r;
}
__device__ __forceinline__ unsigned maj3(unsigned a, unsigned b, unsigned c) {
    unsigned r;
    asm("lop3.b32 %0, %1, %2, %3, 0xE8;" : "=r"(r) : "r"(a), "r"(b), "r"(c));
    return r;
}

// ---------------- device scratch ----------------
__device__ unsigned    g_bits[NPHW];            // layer-1 input bits (padded)
__device__ signed char g_y[(size_t)NHW * 32];   // conv1 halved output (25.7 MB)
__device__ signed char g_y2[(size_t)NHW * 32];  // conv2 halved output (25.7 MB)
__device__ long long g_sum1[32], g_ssq1[32];    // stats of HALVED values
__device__ long long g_sum2[32], g_ssq2[32];
__device__ unsigned  g_wm0[288];
__device__ unsigned  g_wm1[288];

// ---------------- K1: binarize x -> packed bits (8 px/thread) + MERGED PREP -----
__global__ __launch_bounds__(256) void k_pack_x(const float* __restrict__ x,
                                                const float* __restrict__ w1,
                                                const float* __restrict__ w2) {
    int tid = threadIdx.x;
    int bid = blockIdx.x;
    int t = bid * 256 + tid;                      // NHW/8 threads
    size_t p0 = (size_t)t * 8;
    int n = (int)(p0 / HW);
    int q = (int)(p0 % HW);                       // row-contained: 224 % 8 == 0
    unsigned b[8] = {0, 0, 0, 0, 0, 0, 0, 0};
    #pragma unroll
    for (int c = 0; c < 32; c++) {
        const float4* xp = reinterpret_cast<const float4*>(x + ((size_t)(n * 32 + c) * HW + q));
        float4 v0 = __ldcs(xp);
        float4 v1 = __ldcs(xp + 1);
        b[0] |= (v0.x > 0.0f ? 1u : 0u) << c;
        b[1] |= (v0.y > 0.0f ? 1u : 0u) << c;
        b[2] |= (v0.z > 0.0f ? 1u : 0u) << c;
        b[3] |= (v0.w > 0.0f ? 1u : 0u) << c;
        b[4] |= (v1.x > 0.0f ? 1u : 0u) << c;
        b[5] |= (v1.y > 0.0f ? 1u : 0u) << c;
        b[6] |= (v1.z > 0.0f ? 1u : 0u) << c;
        b[7] |= (v1.w > 0.0f ? 1u : 0u) << c;
    }
    int h = q / WW, w = q % WW;
    unsigned* d = g_bits + (size_t)n * PHW + (size_t)(h + 1) * PW + (w + 1);
    #pragma unroll
    for (int i = 0; i < 8; i++) d[i] = b[i];

    // ---- merged prep ----
    if (bid < 57) {                       // border zeroing: 16*900 = 14400 cells
        int i = bid * 256 + tid;
        if (i < NN * 900) {
            int img = i / 900, r = i % 900;
            int hh, ww;
            if (r < 226)      { hh = 0;            ww = r; }
            else if (r < 452) { hh = 225;          ww = r - 226; }
            else if (r < 676) { hh = r - 452 + 1;  ww = 0; }
            else              { hh = r - 676 + 1;  ww = 225; }
            g_bits[(size_t)img * PHW + (size_t)hh * PW + ww] = 0u;
        }
    } else if (bid == 57) {
        for (int i = tid; i < 288; i += 256) {    // strided: 288 entries, 256 threads
            int o = i / 9, tt = i % 9;
            unsigned m = 0;
            #pragma unroll
            for (int k = 0; k < 32; k++)
                m |= (w1[(o * 32 + k) * 9 + tt] > 0.0f ? 1u : 0u) << k;
            g_wm0[i] = m;
        }
    } else if (bid == 58) {
        for (int i = tid; i < 288; i += 256) {
            int o = i / 9, tt = i % 9;
            unsigned m = 0;
            #pragma unroll
            for (int k = 0; k < 32; k++)
                m |= (w2[(o * 32 + k) * 9 + tt] > 0.0f ? 1u : 0u) << k;
            g_wm1[i] = m;
        }
    } else if (bid == 59) {
        if (tid < 32) {
            g_sum1[tid] = 0; g_ssq1[tid] = 0;
            g_sum2[tid] = 0; g_ssq2[tid] = 0;
        }
    }
}

// Per-channel CSA conv step (9->4 popc compressor, masks folded).
__device__ __forceinline__ int conv_ch_csa(
    const unsigned xw[9], unsigned XA, unsigned XB, unsigned XC, unsigned XAll,
    const unsigned m[9], unsigned MR0, unsigned MR1, unsigned MR2, unsigned MAll,
    int base) {
    unsigned c1 = maj3(xw[0] ^ m[0], xw[1] ^ m[1], xw[2] ^ m[2]);
    unsigned c2 = maj3(xw[3] ^ m[3], xw[4] ^ m[4], xw[5] ^ m[5]);
    unsigned c3 = maj3(xw[6] ^ m[6], xw[7] ^ m[7], xw[8] ^ m[8]);
    unsigned s1 = XA ^ MR0;
    unsigned s2 = XB ^ MR1;
    unsigned s3 = XC ^ MR2;
    unsigned s4 = XAll ^ MAll;
    unsigned c4 = maj3(s1, s2, s3);
    unsigned s5 = xor3(c1, c2, c3);
    unsigned c5 = maj3(c1, c2, c3);
    int cnt = __popc(s4) + ((__popc(c4) + __popc(s5)) << 1) + (__popc(c5) << 2);
    return base - cnt;      // base = 144 + half-corrections
}

// ---------------- K2: conv layer 1 — CSA core, 2 channels/warp, X-rotation ------
__global__ __launch_bounds__(512, 2) void k_conv1() {
    int bid   = blockIdx.x;
    int n     = bid / 56;                 // 7 strips * 8 rowblocks
    int rem   = bid % 56;
    int strip = rem % 7;
    int rb    = rem / 7;
    int w0    = strip * 32;
    int h0    = rb * RR;
    int lane  = threadIdx.x;
    int cb    = threadIdx.y * 2;          // 16 warps * 2 channels

    unsigned m[2][9], MR0[2], MR1[2], MR2[2], MAll[2];
    #pragma unroll
    for (int j = 0; j < 2; j++) {
        #pragma unroll
        for (int t = 0; t < 9; t++)
            m[j][t] = g_wm0[(cb + j) * 9 + t];
        MR0[j] = xor3(m[j][0], m[j][1], m[j][2]);
        MR1[j] = xor3(m[j][3], m[j][4], m[j][5]);
        MR2[j] = xor3(m[j][6], m[j][7], m[j][8]);
        MAll[j] = xor3(MR0[j], MR1[j], MR2[j]);
    }

    int w = w0 + lane;
    bool eL = (w == 0), eR = (w == WW - 1);

    int base[2], rctH[2], rcbH[2];
    #pragma unroll
    for (int j = 0; j < 2; j++) {
        int ch[9];
        #pragma unroll
        for (int t = 0; t < 9; t++) ch[t] = 16 - __popc(m[j][t]);   // half-corrections
        int caddH = eL ? -(ch[0] + ch[3] + ch[6]) : (eR ? -(ch[2] + ch[5] + ch[8]) : 0);
        base[j] = 144 + caddH;
        rctH[j] = -(ch[0] + ch[1] + ch[2]) + (eL ? ch[0] : 0) + (eR ? ch[2] : 0);
        rcbH[j] = -(ch[6] + ch[7] + ch[8]) + (eL ? ch[6] : 0) + (eR ? ch[8] : 0);
    }

    const unsigned* bp = g_bits + (size_t)n * PHW + (size_t)h0 * PW + w;
    unsigned xw[9];
    xw[0] = bp[0];  xw[1] = bp[1];      xw[2] = bp[2];
    xw[3] = bp[PW]; xw[4] = bp[PW + 1]; xw[5] = bp[PW + 2];
    unsigned XA = xor3(xw[0], xw[1], xw[2]);
    unsigned XB = xor3(xw[3], xw[4], xw[5]);

    bool top = (h0 == 0), bot = (h0 + RR == HH);
    int rs0 = 0, rs1 = 0, rq0 = 0, rq1 = 0;
    int gidx = cb >> 2;
    int goff = cb & 3;

    #pragma unroll
    for (int rr = 0; rr < RR; rr++) {
        const unsigned* qp = bp + (size_t)(rr + 2) * PW;
        xw[6] = qp[0]; xw[7] = qp[1]; xw[8] = qp[2];

        unsigned XC   = xor3(xw[6], xw[7], xw[8]);
        unsigned XAll = xor3(XA, XB, XC);

        int hv[2];
        #pragma unroll
        for (int j = 0; j < 2; j++) {
            int b = base[j];
            if (rr == 0 && top)      b += rctH[j];
            if (rr == RR - 1 && bot) b += rcbH[j];
            hv[j] = conv_ch_csa(xw, XA, XB, XC, XAll,
                                m[j], MR0[j], MR1[j], MR2[j], MAll[j], b);
        }
        rs0 += hv[0]; rq0 += hv[0] * hv[0];
        rs1 += hv[1]; rq1 += hv[1] * hv[1];

        *reinterpret_cast<short*>(g_y + GY_IDX(n, h0 + rr, gidx, w) + goff) =
            (short)(((unsigned short)(unsigned char)(signed char)hv[0]) |
                    ((unsigned short)(unsigned char)(signed char)hv[1] << 8));

        xw[0] = xw[3]; xw[1] = xw[4]; xw[2] = xw[5];
        xw[3] = xw[6]; xw[4] = xw[7]; xw[5] = xw[8];
        XA = XB; XB = XC;
    }

    int s0 = __reduce_add_sync(0xffffffffu, rs0);
    int q0 = __reduce_add_sync(0xffffffffu, rq0);
    int s1 = __reduce_add_sync(0xffffffffu, rs1);
    int q1 = __reduce_add_sync(0xffffffffu, rq1);
    if (lane == 0) {
        atomicAdd((unsigned long long*)&g_sum1[cb],     (unsigned long long)(long long)s0);
        atomicAdd((unsigned long long*)&g_ssq1[cb],     (unsigned long long)(long long)q0);
        atomicAdd((unsigned long long*)&g_sum1[cb + 1], (unsigned long long)(long long)s1);
        atomicAdd((unsigned long long*)&g_ssq1[cb + 1], (unsigned long long)(long long)q1);
    }
}

// ---------------- K3: FUSED threshold(conv1,BN1) + conv layer 2 (CSA) -----------
__global__ __launch_bounds__(512, 2) void k_conv2p(const float* __restrict__ gamma,
                                                   const float* __restrict__ beta) {
    __shared__ unsigned sBits[RR + 2][35];
    __shared__ int      sTc[32];
    __shared__ unsigned sFl[32];
    __shared__ unsigned sT[8], sF[8];

    int lane = threadIdx.x;
    int tid  = threadIdx.y * 32 + lane;

    int bid   = blockIdx.x;
    int n     = bid / 56;
    int rem   = bid % 56;
    int strip = rem % 7;
    int rb    = rem / 7;
    int w0    = strip * 32;
    int h0    = rb * RR;

    // ---- thresholds from exact integer stats of layer 1 ----
    if (tid < 32) {
        int o = tid;
        double mean = 2.0 * (double)g_sum1[o] / (double)NHW;
        double var  = 4.0 * (double)g_ssq1[o] / (double)NHW - mean * mean;
        double inv  = rsqrt(var + 1e-5);
        double a    = (double)gamma[o] * inv;
        double cst  = (double)beta[o] - mean * a;
        int T; unsigned f;
        if (a > 0.0)      { T = (int)floor(-cst / (2.0 * a));    f = 0x00u; }
        else if (a < 0.0) { T = (int)ceil(-cst / (2.0 * a)) - 1; f = 0xFFu; }
        else              { T = (cst > 0.0) ? -128 : 127;        f = 0x00u; }
        T = max(-128, min(127, T));
        sTc[o] = T & 0xFF;
        sFl[o] = f;
    }
    __syncthreads();
    if (tid < 8) {
        sT[tid] = (unsigned)sTc[4*tid] | ((unsigned)sTc[4*tid+1] << 8)
                | ((unsigned)sTc[4*tid+2] << 16) | ((unsigned)sTc[4*tid+3] << 24);
        sF[tid] = sFl[4*tid] | (sFl[4*tid+1] << 8) | (sFl[4*tid+2] << 16) | (sFl[4*tid+3] << 24);
    }
    __syncthreads();

    // ---- stage thresholded bits (halo tile), dp4a-paired packing ----
    for (int i = tid; i < (RR + 2) * 34; i += 512) {
        int hl = i / 34, wl = i % 34;
        int h = h0 - 1 + hl, w = w0 - 1 + wl;
        unsigned b = 0;
        if ((unsigned)h < HH && (unsigned)w < WW) {
            const unsigned* gp = reinterpret_cast<const unsigned*>(g_y + GY_IDX(n, h, 0, w));
            unsigned p[4];
            #pragma unroll
            for (int pr = 0; pr < 4; pr++) {
                unsigned A0 = gp[(2 * pr)     * WW];
                unsigned A1 = gp[(2 * pr + 1) * WW];
                unsigned m0 = (__vcmpgts4(A0, sT[2*pr])     ^ sF[2*pr])     & 0x01010101u;
                unsigned m1 = (__vcmpgts4(A1, sT[2*pr + 1]) ^ sF[2*pr + 1]) & 0x01010101u;
                unsigned pv = __dp4a(m0, 0x08040201u, 0u);
                p[pr] = __dp4a(m1, 0x80402010u, pv);
            }
            b = p[0] | (p[1] << 8) | (p[2] << 16) | (p[3] << 24);
        }
        sBits[hl][wl] = b;
    }
    __syncthreads();

    // ---- conv from smem: CSA core, 2 channels/warp, X-rotation ----
    int cb = threadIdx.y * 2;
    unsigned m[2][9], MR0[2], MR1[2], MR2[2], MAll[2];
    #pragma unroll
    for (int j = 0; j < 2; j++) {
        #pragma unroll
        for (int t = 0; t < 9; t++)
            m[j][t] = g_wm1[(cb + j) * 9 + t];
        MR0[j] = xor3(m[j][0], m[j][1], m[j][2]);
        MR1[j] = xor3(m[j][3], m[j][4], m[j][5]);
        MR2[j] = xor3(m[j][6], m[j][7], m[j][8]);
        MAll[j] = xor3(MR0[j], MR1[j], MR2[j]);
    }

    int w = w0 + lane;
    bool eL = (w == 0), eR = (w == WW - 1);

    int base[2], rctH[2], rcbH[2];
    #pragma unroll
    for (int j = 0; j < 2; j++) {
        int ch[9];
        #pragma unroll
        for (int t = 0; t < 9; t++) ch[t] = 16 - __popc(m[j][t]);
        int caddH = eL ? -(ch[0] + ch[3] + ch[6]) : (eR ? -(ch[2] + ch[5] + ch[8]) : 0);
        base[j] = 144 + caddH;
        rctH[j] = -(ch[0] + ch[1] + ch[2]) + (eL ? ch[0] : 0) + (eR ? ch[2] : 0);
        rcbH[j] = -(ch[6] + ch[7] + ch[8]) + (eL ? ch[6] : 0) + (eR ? ch[8] : 0);
    }

    unsigned xw[9];
    xw[0] = sBits[0][lane]; xw[1] = sBits[0][lane + 1]; xw[2] = sBits[0][lane + 2];
    xw[3] = sBits[1][lane]; xw[4] = sBits[1][lane + 1]; xw[5] = sBits[1][lane + 2];
    unsigned XA = xor3(xw[0], xw[1], xw[2]);
    unsigned XB = xor3(xw[3], xw[4], xw[5]);

    bool top = (h0 == 0), bot = (h0 + RR == HH);
    int rs0 = 0, rs1 = 0, rq0 = 0, rq1 = 0;
    int gidx = cb >> 2;
    int goff = cb & 3;

    #pragma unroll
    for (int rr = 0; rr < RR; rr++) {
        xw[6] = sBits[rr + 2][lane];
        xw[7] = sBits[rr + 2][lane + 1];
        xw[8] = sBits[rr + 2][lane + 2];

        unsigned XC   = xor3(xw[6], xw[7], xw[8]);
        unsigned XAll = xor3(XA, XB, XC);

        int hv[2];
        #pragma unroll
        for (int j = 0; j < 2; j++) {
            int b = base[j];
            if (rr == 0 && top)      b += rctH[j];
            if (rr == RR - 1 && bot) b += rcbH[j];
            hv[j] = conv_ch_csa(xw, XA, XB, XC, XAll,
                                m[j], MR0[j], MR1[j], MR2[j], MAll[j], b);
        }
        rs0 += hv[0]; rq0 += hv[0] * hv[0];
        rs1 += hv[1]; rq1 += hv[1] * hv[1];

        *reinterpret_cast<short*>(g_y2 + GY_IDX(n, h0 + rr, gidx, w) + goff) =
            (short)(((unsigned short)(unsigned char)(signed char)hv[0]) |
                    ((unsigned short)(unsigned char)(signed char)hv[1] << 8));

        xw[0] = xw[3]; xw[1] = xw[4]; xw[2] = xw[5];
        xw[3] = xw[6]; xw[4] = xw[7]; xw[5] = xw[8];
        XA = XB; XB = XC;
    }

    int s0 = __reduce_add_sync(0xffffffffu, rs0);
    int q0 = __reduce_add_sync(0xffffffffu, rq0);
    int s1 = __reduce_add_sync(0xffffffffu, rs1);
    int q1 = __reduce_add_sync(0xffffffffu, rq1);
    if (lane == 0) {
        atomicAdd((unsigned long long*)&g_sum2[cb],     (unsigned long long)(long long)s0);
        atomicAdd((unsigned long long*)&g_ssq2[cb],     (unsigned long long)(long long)q0);
        atomicAdd((unsigned long long*)&g_sum2[cb + 1], (unsigned long long)(long long)s1);
        atomicAdd((unsigned long long*)&g_ssq2[cb + 1], (unsigned long long)(long long)q1);
    }
}

// ---------------- K4: out = x + a2*(2*yh2) + c2 (8 px/thread, streaming) --------
__global__ __launch_bounds__(256) void k_final(const float* __restrict__ x,
                                               const float* __restrict__ gamma,
                                               const float* __restrict__ beta,
                                               float* __restrict__ out) {
    __shared__ float sa[32], sc[32];
    int o = threadIdx.x;
    if (o < 32) {
        double mean = 2.0 * (double)g_sum2[o] / (double)NHW;
        double var  = 4.0 * (double)g_ssq2[o] / (double)NHW - mean * mean;
        double inv  = rsqrt(var + 1e-5);
        double a    = (double)gamma[o] * inv;
        sa[o] = (float)(2.0 * a);
        sc[o] = (float)((double)beta[o] - mean * a);
    }
    __syncthreads();

    int t = blockIdx.x * 256 + threadIdx.x;       // NHW/8 threads
    size_t p0 = (size_t)t * 8;
    int n = (int)(p0 / HW);
    int q = (int)(p0 % HW);
    int h = q / WW, w = q % WW;                   // w % 8 == 0, all px same row

    #pragma unroll
    for (int g = 0; g < 8; g++) {
        union { uint4 u; signed char s[16]; } A, B;  // signed char: aarch64!
        A.u = *reinterpret_cast<const uint4*>(g_y2 + GY_IDX(n, h, g, w));
        B.u = *reinterpret_cast<const uint4*>(g_y2 + GY_IDX(n, h, g, w + 4));
        #pragma unroll
        for (int j = 0; j < 4; j++) {
            int c = g * 4 + j;
            float a = sa[c], cc = sc[c];
            size_t xi = (size_t)(n * 32 + c) * HW + q;
            const float4* xp = reinterpret_cast<const float4*>(x + xi);
            float4 x0 = __ldcs(xp);
            float4 x1 = __ldcs(xp + 1);
            float4 o0, o1;
            o0.x = x0.x + fmaf(a, (float)A.s[0 + j],  cc);
            o0.y = x0.y + fmaf(a, (float)A.s[4 + j],  cc);
            o0.z = x0.z + fmaf(a, (float)A.s[8 + j],  cc);
            o0.w = x0.w + fmaf(a, (float)A.s[12 + j], cc);
            o1.x = x1.x + fmaf(a, (float)B.s[0 + j],  cc);
            o1.y = x1.y + fmaf(a, (float)B.s[4 + j],  cc);
            o1.z = x1.z + fmaf(a, (float)B.s[8 + j],  cc);
            o1.w = x1.w + fmaf(a, (float)B.s[12 + j], cc);
            float4* op = reinterpret_cast<float4*>(out + xi);
            __stcs(op, o0);
            __stcs(op + 1, o1);
        }
    }
}

// ---------------- launch ----------------
extern "C" void kernel_launch(void* const* d_in, const int* in_sizes, int n_in,
                              void* d_out, int out_size) {
    const float* x  = (const float*)d_in[0];
    const float* w1 = (const float*)d_in[1];
    const float* g1 = (const float*)d_in[2];
    const float* b1 = (const float*)d_in[3];
    const float* w2 = (const float*)d_in[4];
    const float* g2 = (const float*)d_in[5];
    const float* b2 = (const float*)d_in[6];
    float* out = (float*)d_out;

    k_pack_x<<<NHW / 8 / 256, 256>>>(x, w1, w2);
    k_conv1<<<NN * 7 * (HH / RR), dim3(32, 16)>>>();
    k_conv2p<<<NN * 7 * (HH / RR), dim3(32, 16)>>>(g1, b1);
    k_final<<<NHW / 8 / 256, 256>>>(x, g2, b2, out);
}

// round 17
// speedup vs baseline: 1.1760x; 1.0008x over previous
#include <cuda_runtime.h>
#include <cstdint>

#define NN 16
#define CC 32
#define HH 224
#define WW 224
#define HW (HH * WW)            // 50176
#define NHW (NN * HW)           // 802816
#define PW 226
#define PH 226
#define PHW (PW * PH)           // 51076
#define NPHW (NN * PHW)         // 817216
#define RR 28                   // rows per conv block (224/28 = 8 row-blocks)

// g_y layout: [n][h][group(8)][w][4ch] int8 (halved conv values).
#define GY_IDX(n, h, g, w) (((((size_t)(n) * HH + (h)) * 8 + (g)) * WW + (w)) * 4)

// ---------------- CSA helpers (single-LOP3 xor3 / majority) ----------------
__device__ __forceinline__ unsigned xor3(unsigned a, unsigned b, unsigned c) {
    unsigned r;
    asm("lop3.b32 %0, %1, %2, %3, 0x96;" : "=r"(r) : "r"(a), "r"(b), "r"(c));
    return r;
}
__device__ __forceinline__ unsigned maj3(unsigned a, unsigned b, unsigned c) {
    unsigned r;
    asm("lop3.b32 %0, %1, %2, %3, 0xE8;" : "=r"(r) : "r"(a), "r"(b), "r"(c));
    return r;
}

// ---------------- device scratch ----------------
__device__ unsigned    g_bits[NPHW];            // layer-1 input bits (padded)
__device__ signed char g_y[(size_t)NHW * 32];   // conv1 halved output (25.7 MB)
__device__ signed char g_y2[(size_t)NHW * 32];  // conv2 halved output (25.7 MB)
__device__ long long g_sum1[32], g_ssq1[32];    // stats of HALVED values
__device__ long long g_sum2[32], g_ssq2[32];
__device__ unsigned  g_wm0[288];
__device__ unsigned  g_wm1[288];

// ---------------- K1: binarize x -> packed bits (8 px/thread) + MERGED PREP -----
__global__ __launch_bounds__(256) void k_pack_x(const float* __restrict__ x,
                                                const float* __restrict__ w1,
                                                const float* __restrict__ w2) {
    int tid = threadIdx.x;
    int bid = blockIdx.x;
    int t = bid * 256 + tid;                      // NHW/8 threads
    size_t p0 = (size_t)t * 8;
    int n = (int)(p0 / HW);
    int q = (int)(p0 % HW);                       // row-contained: 224 % 8 == 0
    unsigned b[8] = {0, 0, 0, 0, 0, 0, 0, 0};
    #pragma unroll
    for (int c = 0; c < 32; c++) {
        const float4* xp = reinterpret_cast<const float4*>(x + ((size_t)(n * 32 + c) * HW + q));
        float4 v0 = __ldcs(xp);
        float4 v1 = __ldcs(xp + 1);
        b[0] |= (v0.x > 0.0f ? 1u : 0u) << c;
        b[1] |= (v0.y > 0.0f ? 1u : 0u) << c;
        b[2] |= (v0.z > 0.0f ? 1u : 0u) << c;
        b[3] |= (v0.w > 0.0f ? 1u : 0u) << c;
        b[4] |= (v1.x > 0.0f ? 1u : 0u) << c;
        b[5] |= (v1.y > 0.0f ? 1u : 0u) << c;
        b[6] |= (v1.z > 0.0f ? 1u : 0u) << c;
        b[7] |= (v1.w > 0.0f ? 1u : 0u) << c;
    }
    int h = q / WW, w = q % WW;
    unsigned* d = g_bits + (size_t)n * PHW + (size_t)(h + 1) * PW + (w + 1);
    #pragma unroll
    for (int i = 0; i < 8; i++) d[i] = b[i];

    // ---- merged prep ----
    if (bid < 57) {                       // border zeroing: 16*900 = 14400 cells
        int i = bid * 256 + tid;
        if (i < NN * 900) {
            int img = i / 900, r = i % 900;
            int hh, ww;
            if (r < 226)      { hh = 0;            ww = r; }
            else if (r < 452) { hh = 225;          ww = r - 226; }
            else if (r < 676) { hh = r - 452 + 1;  ww = 0; }
            else              { hh = r - 676 + 1;  ww = 225; }
            g_bits[(size_t)img * PHW + (size_t)hh * PW + ww] = 0u;
        }
    } else if (bid == 57) {
        for (int i = tid; i < 288; i += 256) {    // strided: 288 entries, 256 threads
            int o = i / 9, tt = i % 9;
            unsigned m = 0;
            #pragma unroll
            for (int k = 0; k < 32; k++)
                m |= (w1[(o * 32 + k) * 9 + tt] > 0.0f ? 1u : 0u) << k;
            g_wm0[i] = m;
        }
    } else if (bid == 58) {
        for (int i = tid; i < 288; i += 256) {
            int o = i / 9, tt = i % 9;
            unsigned m = 0;
            #pragma unroll
            for (int k = 0; k < 32; k++)
                m |= (w2[(o * 32 + k) * 9 + tt] > 0.0f ? 1u : 0u) << k;
            g_wm1[i] = m;
        }
    } else if (bid == 59) {
        if (tid < 32) {
            g_sum1[tid] = 0; g_ssq1[tid] = 0;
            g_sum2[tid] = 0; g_ssq2[tid] = 0;
        }
    }
}

// Per-channel CSA conv step (9->4 popc compressor, masks folded).
__device__ __forceinline__ int conv_ch_csa(
    const unsigned xw[9], unsigned XA, unsigned XB, unsigned XC, unsigned XAll,
    const unsigned m[9], unsigned MR0, unsigned MR1, unsigned MR2, unsigned MAll,
    int base) {
    unsigned c1 = maj3(xw[0] ^ m[0], xw[1] ^ m[1], xw[2] ^ m[2]);
    unsigned c2 = maj3(xw[3] ^ m[3], xw[4] ^ m[4], xw[5] ^ m[5]);
    unsigned c3 = maj3(xw[6] ^ m[6], xw[7] ^ m[7], xw[8] ^ m[8]);
    unsigned s1 = XA ^ MR0;
    unsigned s2 = XB ^ MR1;
    unsigned s3 = XC ^ MR2;
    unsigned s4 = XAll ^ MAll;
    unsigned c4 = maj3(s1, s2, s3);
    unsigned s5 = xor3(c1, c2, c3);
    unsigned c5 = maj3(c1, c2, c3);
    int cnt = __popc(s4) + ((__popc(c4) + __popc(s5)) << 1) + (__popc(c5) << 2);
    return base - cnt;      // base = 144 + half-corrections
}

// ---------------- K2: conv layer 1 — CSA core, 2 channels/warp, X-rotation ------
__global__ __launch_bounds__(512, 2) void k_conv1() {
    int bid   = blockIdx.x;
    int n     = bid / 56;                 // 7 strips * 8 rowblocks
    int rem   = bid % 56;
    int strip = rem % 7;
    int rb    = rem / 7;
    int w0    = strip * 32;
    int h0    = rb * RR;
    int lane  = threadIdx.x;
    int cb    = threadIdx.y * 2;          // 16 warps * 2 channels

    unsigned m[2][9], MR0[2], MR1[2], MR2[2], MAll[2];
    #pragma unroll
    for (int j = 0; j < 2; j++) {
        #pragma unroll
        for (int t = 0; t < 9; t++)
            m[j][t] = g_wm0[(cb + j) * 9 + t];
        MR0[j] = xor3(m[j][0], m[j][1], m[j][2]);
        MR1[j] = xor3(m[j][3], m[j][4], m[j][5]);
        MR2[j] = xor3(m[j][6], m[j][7], m[j][8]);
        MAll[j] = xor3(MR0[j], MR1[j], MR2[j]);
    }

    int w = w0 + lane;
    bool eL = (w == 0), eR = (w == WW - 1);

    int base[2], rctH[2], rcbH[2];
    #pragma unroll
    for (int j = 0; j < 2; j++) {
        int ch[9];
        #pragma unroll
        for (int t = 0; t < 9; t++) ch[t] = 16 - __popc(m[j][t]);   // half-corrections
        int caddH = eL ? -(ch[0] + ch[3] + ch[6]) : (eR ? -(ch[2] + ch[5] + ch[8]) : 0);
        base[j] = 144 + caddH;
        rctH[j] = -(ch[0] + ch[1] + ch[2]) + (eL ? ch[0] : 0) + (eR ? ch[2] : 0);
        rcbH[j] = -(ch[6] + ch[7] + ch[8]) + (eL ? ch[6] : 0) + (eR ? ch[8] : 0);
    }

    const unsigned* bp = g_bits + (size_t)n * PHW + (size_t)h0 * PW + w;
    unsigned xw[9];
    xw[0] = bp[0];  xw[1] = bp[1];      xw[2] = bp[2];
    xw[3] = bp[PW]; xw[4] = bp[PW + 1]; xw[5] = bp[PW + 2];
    unsigned XA = xor3(xw[0], xw[1], xw[2]);
    unsigned XB = xor3(xw[3], xw[4], xw[5]);

    bool top = (h0 == 0), bot = (h0 + RR == HH);
    int rs0 = 0, rs1 = 0, rq0 = 0, rq1 = 0;
    int gidx = cb >> 2;
    int goff = cb & 3;

    #pragma unroll
    for (int rr = 0; rr < RR; rr++) {
        const unsigned* qp = bp + (size_t)(rr + 2) * PW;
        xw[6] = qp[0]; xw[7] = qp[1]; xw[8] = qp[2];

        unsigned XC   = xor3(xw[6], xw[7], xw[8]);
        unsigned XAll = xor3(XA, XB, XC);

        int hv[2];
        #pragma unroll
        for (int j = 0; j < 2; j++) {
            int b = base[j];
            if (rr == 0 && top)      b += rctH[j];
            if (rr == RR - 1 && bot) b += rcbH[j];
            hv[j] = conv_ch_csa(xw, XA, XB, XC, XAll,
                                m[j], MR0[j], MR1[j], MR2[j], MAll[j], b);
        }
        rs0 += hv[0]; rq0 += hv[0] * hv[0];
        rs1 += hv[1]; rq1 += hv[1] * hv[1];

        *reinterpret_cast<short*>(g_y + GY_IDX(n, h0 + rr, gidx, w) + goff) =
            (short)(((unsigned short)(unsigned char)(signed char)hv[0]) |
                    ((unsigned short)(unsigned char)(signed char)hv[1] << 8));

        xw[0] = xw[3]; xw[1] = xw[4]; xw[2] = xw[5];
        xw[3] = xw[6]; xw[4] = xw[7]; xw[5] = xw[8];
        XA = XB; XB = XC;
    }

    int s0 = __reduce_add_sync(0xffffffffu, rs0);
    int q0 = __reduce_add_sync(0xffffffffu, rq0);
    int s1 = __reduce_add_sync(0xffffffffu, rs1);
    int q1 = __reduce_add_sync(0xffffffffu, rq1);
    if (lane == 0) {
        atomicAdd((unsigned long long*)&g_sum1[cb],     (unsigned long long)(long long)s0);
        atomicAdd((unsigned long long*)&g_ssq1[cb],     (unsigned long long)(long long)q0);
        atomicAdd((unsigned long long*)&g_sum1[cb + 1], (unsigned long long)(long long)s1);
        atomicAdd((unsigned long long*)&g_ssq1[cb + 1], (unsigned long long)(long long)q1);
    }
}

// ---------------- K3: FUSED threshold(conv1,BN1) + conv layer 2 (CSA) -----------
__global__ __launch_bounds__(512, 2) void k_conv2p(const float* __restrict__ gamma,
                                                   const float* __restrict__ beta) {
    __shared__ unsigned sBits[RR + 2][35];
    __shared__ int      sTc[32];
    __shared__ unsigned sFl[32];
    __shared__ unsigned sT[8], sF[8];

    int lane = threadIdx.x;
    int tid  = threadIdx.y * 32 + lane;

    int bid   = blockIdx.x;
    int n     = bid / 56;
    int rem   = bid % 56;
    int strip = rem % 7;
    int rb    = rem / 7;
    int w0    = strip * 32;
    int h0    = rb * RR;

    // ---- thresholds from exact integer stats of layer 1 ----
    if (tid < 32) {
        int o = tid;
        double mean = 2.0 * (double)g_sum1[o] / (double)NHW;
        double var  = 4.0 * (double)g_ssq1[o] / (double)NHW - mean * mean;
        double inv  = rsqrt(var + 1e-5);
        double a    = (double)gamma[o] * inv;
        double cst  = (double)beta[o] - mean * a;
        int T; unsigned f;
        if (a > 0.0)      { T = (int)floor(-cst / (2.0 * a));    f = 0x00u; }
        else if (a < 0.0) { T = (int)ceil(-cst / (2.0 * a)) - 1; f = 0xFFu; }
        else              { T = (cst > 0.0) ? -128 : 127;        f = 0x00u; }
        T = max(-128, min(127, T));
        sTc[o] = T & 0xFF;
        sFl[o] = f;
    }
    __syncthreads();
    if (tid < 8) {
        sT[tid] = (unsigned)sTc[4*tid] | ((unsigned)sTc[4*tid+1] << 8)
                | ((unsigned)sTc[4*tid+2] << 16) | ((unsigned)sTc[4*tid+3] << 24);
        sF[tid] = sFl[4*tid] | (sFl[4*tid+1] << 8) | (sFl[4*tid+2] << 16) | (sFl[4*tid+3] << 24);
    }
    __syncthreads();

    // ---- stage thresholded bits (halo tile), dp4a-paired packing ----
    for (int i = tid; i < (RR + 2) * 34; i += 512) {
        int hl = i / 34, wl = i % 34;
        int h = h0 - 1 + hl, w = w0 - 1 + wl;
        unsigned b = 0;
        if ((unsigned)h < HH && (unsigned)w < WW) {
            const unsigned* gp = reinterpret_cast<const unsigned*>(g_y + GY_IDX(n, h, 0, w));
            unsigned p[4];
            #pragma unroll
            for (int pr = 0; pr < 4; pr++) {
                unsigned A0 = gp[(2 * pr)     * WW];
                unsigned A1 = gp[(2 * pr + 1) * WW];
                unsigned m0 = (__vcmpgts4(A0, sT[2*pr])     ^ sF[2*pr])     & 0x01010101u;
                unsigned m1 = (__vcmpgts4(A1, sT[2*pr + 1]) ^ sF[2*pr + 1]) & 0x01010101u;
                unsigned pv = __dp4a(m0, 0x08040201u, 0u);
                p[pr] = __dp4a(m1, 0x80402010u, pv);
            }
            b = p[0] | (p[1] << 8) | (p[2] << 16) | (p[3] << 24);
        }
        sBits[hl][wl] = b;
    }
    __syncthreads();

    // ---- conv from smem: CSA core, 2 channels/warp, X-rotation ----
    int cb = threadIdx.y * 2;
    unsigned m[2][9], MR0[2], MR1[2], MR2[2], MAll[2];
    #pragma unroll
    for (int j = 0; j < 2; j++) {
        #pragma unroll
        for (int t = 0; t < 9; t++)
            m[j][t] = g_wm1[(cb + j) * 9 + t];
        MR0[j] = xor3(m[j][0], m[j][1], m[j][2]);
        MR1[j] = xor3(m[j][3], m[j][4], m[j][5]);
        MR2[j] = xor3(m[j][6], m[j][7], m[j][8]);
        MAll[j] = xor3(MR0[j], MR1[j], MR2[j]);
    }

    int w = w0 + lane;
    bool eL = (w == 0), eR = (w == WW - 1);

    int base[2], rctH[2], rcbH[2];
    #pragma unroll
    for (int j = 0; j < 2; j++) {
        int ch[9];
        #pragma unroll
        for (int t = 0; t < 9; t++) ch[t] = 16 - __popc(m[j][t]);
        int caddH = eL ? -(ch[0] + ch[3] + ch[6]) : (eR ? -(ch[2] + ch[5] + ch[8]) : 0);
        base[j] = 144 + caddH;
        rctH[j] = -(ch[0] + ch[1] + ch[2]) + (eL ? ch[0] : 0) + (eR ? ch[2] : 0);
        rcbH[j] = -(ch[6] + ch[7] + ch[8]) + (eL ? ch[6] : 0) + (eR ? ch[8] : 0);
    }

    unsigned xw[9];
    xw[0] = sBits[0][lane]; xw[1] = sBits[0][lane + 1]; xw[2] = sBits[0][lane + 2];
    xw[3] = sBits[1][lane]; xw[4] = sBits[1][lane + 1]; xw[5] = sBits[1][lane + 2];
    unsigned XA = xor3(xw[0], xw[1], xw[2]);
    unsigned XB = xor3(xw[3], xw[4], xw[5]);

    bool top = (h0 == 0), bot = (h0 + RR == HH);
    int rs0 = 0, rs1 = 0, rq0 = 0, rq1 = 0;
    int gidx = cb >> 2;
    int goff = cb & 3;

    #pragma unroll
    for (int rr = 0; rr < RR; rr++) {
        xw[6] = sBits[rr + 2][lane];
        xw[7] = sBits[rr + 2][lane + 1];
        xw[8] = sBits[rr + 2][lane + 2];

        unsigned XC   = xor3(xw[6], xw[7], xw[8]);
        unsigned XAll = xor3(XA, XB, XC);

        int hv[2];
        #pragma unroll
        for (int j = 0; j < 2; j++) {
            int b = base[j];
            if (rr == 0 && top)      b += rctH[j];
            if (rr == RR - 1 && bot) b += rcbH[j];
            hv[j] = conv_ch_csa(xw, XA, XB, XC, XAll,
                                m[j], MR0[j], MR1[j], MR2[j], MAll[j], b);
        }
        rs0 += hv[0]; rq0 += hv[0] * hv[0];
        rs1 += hv[1]; rq1 += hv[1] * hv[1];

        *reinterpret_cast<short*>(g_y2 + GY_IDX(n, h0 + rr, gidx, w) + goff) =
            (short)(((unsigned short)(unsigned char)(signed char)hv[0]) |
                    ((unsigned short)(unsigned char)(signed char)hv[1] << 8));

        xw[0] = xw[3]; xw[1] = xw[4]; xw[2] = xw[5];
        xw[3] = xw[6]; xw[4] = xw[7]; xw[5] = xw[8];
        XA = XB; XB = XC;
    }

    int s0 = __reduce_add_sync(0xffffffffu, rs0);
    int q0 = __reduce_add_sync(0xffffffffu, rq0);
    int s1 = __reduce_add_sync(0xffffffffu, rs1);
    int q1 = __reduce_add_sync(0xffffffffu, rq1);
    if (lane == 0) {
        atomicAdd((unsigned long long*)&g_sum2[cb],     (unsigned long long)(long long)s0);
        atomicAdd((unsigned long long*)&g_ssq2[cb],     (unsigned long long)(long long)q0);
        atomicAdd((unsigned long long*)&g_sum2[cb + 1], (unsigned long long)(long long)s1);
        atomicAdd((unsigned long long*)&g_ssq2[cb + 1], (unsigned long long)(long long)q1);
    }
}

// ---------------- K4: out = x + a2*(2*yh2) + c2 (4 px/thread, streaming) --------
__global__ __launch_bounds__(256) void k_final(const float* __restrict__ x,
                                               const float* __restrict__ gamma,
                                               const float* __restrict__ beta,
                                               float* __restrict__ out) {
    __shared__ float sa[32], sc[32];
    int o = threadIdx.x;
    if (o < 32) {
        double mean = 2.0 * (double)g_sum2[o] / (double)NHW;
        double var  = 4.0 * (double)g_ssq2[o] / (double)NHW - mean * mean;
        double inv  = rsqrt(var + 1e-5);
        double a    = (double)gamma[o] * inv;
        sa[o] = (float)(2.0 * a);
        sc[o] = (float)((double)beta[o] - mean * a);
    }
    __syncthreads();

    int t = blockIdx.x * 256 + threadIdx.x;       // NHW/4 threads
    size_t p0 = (size_t)t * 4;
    int n = (int)(p0 / HW);
    int q = (int)(p0 % HW);
    int h = q / WW, w = q % WW;                   // w % 4 == 0

    #pragma unroll
    for (int g = 0; g < 8; g++) {
        union { uint4 u; signed char s[16]; } A;  // signed char: aarch64!
        A.u = *reinterpret_cast<const uint4*>(g_y2 + GY_IDX(n, h, g, w));
        #pragma unroll
        for (int j = 0; j < 4; j++) {
            int c = g * 4 + j;
            float a = sa[c], cc = sc[c];
            size_t xi = (size_t)(n * 32 + c) * HW + q;
            float4 xv = __ldcs(reinterpret_cast<const float4*>(x + xi));
            float4 o4;
            o4.x = xv.x + fmaf(a, (float)A.s[0 + j],  cc);
            o4.y = xv.y + fmaf(a, (float)A.s[4 + j],  cc);
            o4.z = xv.z + fmaf(a, (float)A.s[8 + j],  cc);
            o4.w = xv.w + fmaf(a, (float)A.s[12 + j], cc);
            __stcs(reinterpret_cast<float4*>(out + xi), o4);
        }
    }
}

// ---------------- launch ----------------
extern "C" void kernel_launch(void* const* d_in, const int* in_sizes, int n_in,
                              void* d_out, int out_size) {
    const float* x  = (const float*)d_in[0];
    const float* w1 = (const float*)d_in[1];
    const float* g1 = (const float*)d_in[2];
    const float* b1 = (const float*)d_in[3];
    const float* w2 = (const float*)d_in[4];
    const float* g2 = (const float*)d_in[5];
    const float* b2 = (const float*)d_in[6];
    float* out = (float*)d_out;

    k_pack_x<<<NHW / 8 / 256, 256>>>(x, w1, w2);
    k_conv1<<<NN * 7 * (HH / RR), dim3(32, 16)>>>();
    k_conv2p<<<NN * 7 * (HH / RR), dim3(32, 16)>>>(g1, b1);
    k_final<<<NHW / 4 / 256, 256>>>(x, g2, b2, out);
}